// round 13
// baseline (speedup 1.0000x reference)
#include <cuda_runtime.h>
#include <math.h>
#include <stdint.h>

#define BATCH 4
#define SEQ   2048
#define DIM   1024
#define DIMW  512            // bf16x2 words per row
#define NH    16
#define HD    64
#define HDW   32             // bf16x2 words per head row
#define MROWS (BATCH*SEQ)    // 8192
#define N3    (3*DIM)        // 3072
#define NROWS (BATCH*NH*SEQ) // 131072 head rows

// logit bound in exp2 domain: 8*log2(e) = 11.5416
#define FIXED_MAX 11.6f
#define QSCALE (8.0f * 1.4426950408889634f)

// ---------------- scratch (device globals; referenced ONLY in device code) --
__device__ __align__(16) unsigned g_hw[MROWS * DIMW];        // LN out, bf16x2
__device__ __align__(16) unsigned g_wq[(size_t)N3 * DIMW];   // qkv_w bf16
__device__ __align__(16) unsigned g_wo[(size_t)DIM * DIMW];  // out_w bf16
__device__ __align__(16) unsigned g_qw[(size_t)NROWS * HDW]; // q bf16 [bh][t][dw]
__device__ __align__(16) unsigned g_kw[(size_t)NROWS * HDW];
__device__ __align__(16) unsigned g_vw[(size_t)NROWS * HDW];
__device__ __align__(16) unsigned g_ow[MROWS * DIMW];        // attn out, bf16x2

// ---------------- helpers -----------------------------------------------------
__device__ __forceinline__ unsigned packbf(float lo, float hi) {
    unsigned d;
    asm("cvt.rn.bf16x2.f32 %0, %1, %2;" : "=r"(d) : "f"(hi), "f"(lo));
    return d;
}
__device__ __forceinline__ float ex2(float x) {
    float r;
    asm("ex2.approx.f32 %0, %1;" : "=f"(r) : "f"(x));
    return r;
}
__device__ __forceinline__ unsigned prmt(unsigned a, unsigned b, unsigned s) {
    unsigned d;
    asm("prmt.b32 %0, %1, %2, %3;" : "=r"(d) : "r"(a), "r"(b), "r"(s));
    return d;
}
__device__ __forceinline__ void mmabf(float4& d, unsigned a0, unsigned a1,
                                      unsigned a2, unsigned a3,
                                      unsigned b0, unsigned b1) {
    asm volatile(
        "mma.sync.aligned.m16n8k16.row.col.f32.bf16.bf16.f32 "
        "{%0,%1,%2,%3}, {%4,%5,%6,%7}, {%8,%9}, {%0,%1,%2,%3};\n"
        : "+f"(d.x), "+f"(d.y), "+f"(d.z), "+f"(d.w)
        : "r"(a0), "r"(a1), "r"(a2), "r"(a3), "r"(b0), "r"(b1));
}

// ---------------- weight fp32 -> bf16 conversion (once per call) -------------
__global__ __launch_bounds__(256) void wconv(const float* __restrict__ qkvw,
                                             const float* __restrict__ outw) {
    size_t i = (size_t)blockIdx.x * 256 + threadIdx.x;
    const size_t NQ = (size_t)N3 * DIMW;
    const size_t NO = (size_t)DIM * DIMW;
    if (i < NQ) {
        float2 v = *(const float2*)(qkvw + 2 * i);
        g_wq[i] = packbf(v.x, v.y);
    }
    if (i < NO) {
        float2 v = *(const float2*)(outw + 2 * i);
        g_wo[i] = packbf(v.x, v.y);
    }
}

// ---------------- LayerNorm (fp32 math, bf16 output) ------------------------
__global__ __launch_bounds__(256) void ln_kernel(const float* __restrict__ x,
                                                 const float* __restrict__ w,
                                                 const float* __restrict__ b) {
    int row = blockIdx.x;
    const float4 v = ((const float4*)(x + (size_t)row * DIM))[threadIdx.x];
    float s  = v.x + v.y + v.z + v.w;
    float ss = v.x*v.x + v.y*v.y + v.z*v.z + v.w*v.w;

    __shared__ float sh_s[8], sh_ss[8];
    #pragma unroll
    for (int o = 16; o > 0; o >>= 1) {
        s  += __shfl_xor_sync(0xffffffffu, s,  o);
        ss += __shfl_xor_sync(0xffffffffu, ss, o);
    }
    int wid = threadIdx.x >> 5, lid = threadIdx.x & 31;
    if (lid == 0) { sh_s[wid] = s; sh_ss[wid] = ss; }
    __syncthreads();
    if (wid == 0) {
        s  = (lid < 8) ? sh_s[lid]  : 0.0f;
        ss = (lid < 8) ? sh_ss[lid] : 0.0f;
        #pragma unroll
        for (int o = 4; o > 0; o >>= 1) {
            s  += __shfl_xor_sync(0xffffffffu, s,  o);
            ss += __shfl_xor_sync(0xffffffffu, ss, o);
        }
        if (lid == 0) { sh_s[0] = s; sh_ss[0] = ss; }
    }
    __syncthreads();
    float mean = sh_s[0] * (1.0f / DIM);
    float var  = sh_ss[0] * (1.0f / DIM) - mean * mean;
    float rstd = rsqrtf(var + 1e-5f);

    const float4 wv = ((const float4*)w)[threadIdx.x];
    const float4 bv = ((const float4*)b)[threadIdx.x];
    uint2 out;
    out.x = packbf((v.x - mean) * rstd * wv.x + bv.x,
                   (v.y - mean) * rstd * wv.y + bv.y);
    out.y = packbf((v.z - mean) * rstd * wv.z + bv.z,
                   (v.w - mean) * rstd * wv.w + bv.w);
    *(uint2*)&g_hw[(size_t)row * DIMW + threadIdx.x * 2] = out;
}

// ---------------- bf16 mma.sync GEMM, double-buffered ------------------------
// MODE 0: A=g_hw, B=g_wq, fused bias + per-head L2 norm, bf16 scatter to q/k/v.
// MODE 1: A=g_ow, B=g_wo, y = C + bias + x (fp32).
__device__ __forceinline__ void scatter2(int m, int n, float v0, float v1) {
    int which = n >> 10;
    int hn = n & 1023;
    int head = hn >> 6, d = hn & 63;
    unsigned* dst = (which == 0) ? g_qw : (which == 1) ? g_kw : g_vw;
    int bb = m >> 11, t = m & 2047;
    dst[(((size_t)(bb * NH + head)) * SEQ + t) * HDW + (d >> 1)] = packbf(v0, v1);
}

template<int MODE>
__global__ __launch_bounds__(256) void gemm_bf(const float* __restrict__ bias,
                                               const float* __restrict__ x,
                                               float* __restrict__ y) {
    const unsigned* Asrc = (MODE == 0) ? g_hw : g_ow;
    const unsigned* Bsrc = (MODE == 0) ? g_wq : g_wo;
    __shared__ unsigned Aw[2][128 * 20];
    __shared__ unsigned Bw[2][128 * 20];

    const int tid = threadIdx.x;
    const int w = tid >> 5, lane = tid & 31;
    const int g = lane >> 2, j = lane & 3;
    const int wm = w & 3, wn = w >> 2;
    const int m0 = blockIdx.y * 128;
    const int n0 = blockIdx.x * 128;

    const unsigned* ag = Asrc + (size_t)m0 * DIMW;
    const unsigned* bg = Bsrc + (size_t)n0 * DIMW;
    const int r0l = tid >> 2, q0l = (tid & 3) * 4;
    const int r1l = (tid + 256) >> 2, q1l = q0l;

    float4 c[2][8];
    #pragma unroll
    for (int mt = 0; mt < 2; mt++)
        #pragma unroll
        for (int nt = 0; nt < 8; nt++) c[mt][nt] = make_float4(0.f, 0.f, 0.f, 0.f);

    uint4 pa0, pa1, pb0, pb1;
    pa0 = *(const uint4*)(ag + (size_t)r0l * DIMW + q0l);
    pa1 = *(const uint4*)(ag + (size_t)r1l * DIMW + q1l);
    pb0 = *(const uint4*)(bg + (size_t)r0l * DIMW + q0l);
    pb1 = *(const uint4*)(bg + (size_t)r1l * DIMW + q1l);
    *(uint4*)&Aw[0][r0l * 20 + q0l] = pa0;
    *(uint4*)&Aw[0][r1l * 20 + q1l] = pa1;
    *(uint4*)&Bw[0][r0l * 20 + q0l] = pb0;
    *(uint4*)&Bw[0][r1l * 20 + q1l] = pb1;
    __syncthreads();

    for (int kt = 0; kt < 32; kt++) {
        const int cur = kt & 1, nxt = cur ^ 1;
        if (kt + 1 < 32) {
            int ko = (kt + 1) * 16;
            pa0 = *(const uint4*)(ag + (size_t)r0l * DIMW + ko + q0l);
            pa1 = *(const uint4*)(ag + (size_t)r1l * DIMW + ko + q1l);
            pb0 = *(const uint4*)(bg + (size_t)r0l * DIMW + ko + q0l);
            pb1 = *(const uint4*)(bg + (size_t)r1l * DIMW + ko + q1l);
        }

        #pragma unroll
        for (int kc = 0; kc < 2; kc++) {
            unsigned a[2][4];
            #pragma unroll
            for (int mt = 0; mt < 2; mt++) {
                int row = wm * 32 + mt * 16 + g;
                a[mt][0] = Aw[cur][row * 20 + kc * 8 + j];
                a[mt][1] = Aw[cur][(row + 8) * 20 + kc * 8 + j];
                a[mt][2] = Aw[cur][row * 20 + kc * 8 + j + 4];
                a[mt][3] = Aw[cur][(row + 8) * 20 + kc * 8 + j + 4];
            }
            unsigned b0[8], b1[8];
            #pragma unroll
            for (int nt = 0; nt < 8; nt++) {
                int n = wn * 64 + nt * 8 + g;
                b0[nt] = Bw[cur][n * 20 + kc * 8 + j];
                b1[nt] = Bw[cur][n * 20 + kc * 8 + j + 4];
            }
            #pragma unroll
            for (int mt = 0; mt < 2; mt++)
                #pragma unroll
                for (int nt = 0; nt < 8; nt++)
                    mmabf(c[mt][nt], a[mt][0], a[mt][1], a[mt][2], a[mt][3],
                          b0[nt], b1[nt]);
        }

        if (kt + 1 < 32) {
            *(uint4*)&Aw[nxt][r0l * 20 + q0l] = pa0;
            *(uint4*)&Aw[nxt][r1l * 20 + q1l] = pa1;
            *(uint4*)&Bw[nxt][r0l * 20 + q0l] = pb0;
            *(uint4*)&Bw[nxt][r1l * 20 + q1l] = pb1;
        }
        __syncthreads();
    }

    if (MODE == 0) {
        // warp's 64-col span = exactly one head; lanes 4g+j form the quad
        const int which = (n0 + wn * 64) >> 10;        // 0=q, 1=k, 2=v
        const float sc = (which == 0) ? QSCALE : 1.0f;
        #pragma unroll
        for (int mt = 0; mt < 2; mt++) {
            int r0 = m0 + wm * 32 + mt * 16 + g;
            int r1 = r0 + 8;
            float v0[16], v1[16];
            float ss0 = 0.f, ss1 = 0.f;
            #pragma unroll
            for (int nt = 0; nt < 8; nt++) {
                int n = n0 + wn * 64 + nt * 8 + 2 * j;
                float bv0 = bias[n], bv1 = bias[n + 1];
                v0[2*nt]   = c[mt][nt].x + bv0;
                v0[2*nt+1] = c[mt][nt].y + bv1;
                v1[2*nt]   = c[mt][nt].z + bv0;
                v1[2*nt+1] = c[mt][nt].w + bv1;
                ss0 += v0[2*nt]*v0[2*nt] + v0[2*nt+1]*v0[2*nt+1];
                ss1 += v1[2*nt]*v1[2*nt] + v1[2*nt+1]*v1[2*nt+1];
            }
            float rn0 = 1.f, rn1 = 1.f;
            if (which < 2) {
                #pragma unroll
                for (int off = 1; off <= 2; off <<= 1) {
                    ss0 += __shfl_xor_sync(0xffffffffu, ss0, off);
                    ss1 += __shfl_xor_sync(0xffffffffu, ss1, off);
                }
                rn0 = sc / fmaxf(sqrtf(ss0), 1e-12f);
                rn1 = sc / fmaxf(sqrtf(ss1), 1e-12f);
            }
            #pragma unroll
            for (int nt = 0; nt < 8; nt++) {
                int n = n0 + wn * 64 + nt * 8 + 2 * j;
                scatter2(r0, n, v0[2*nt] * rn0, v0[2*nt+1] * rn0);
                scatter2(r1, n, v1[2*nt] * rn1, v1[2*nt+1] * rn1);
            }
        }
    } else {
        #pragma unroll
        for (int mt = 0; mt < 2; mt++) {
            int r0 = m0 + wm * 32 + mt * 16 + g;
            int r1 = r0 + 8;
            #pragma unroll
            for (int nt = 0; nt < 8; nt++) {
                int n = n0 + wn * 64 + nt * 8 + 2 * j;
                float bv0 = bias[n], bv1 = bias[n + 1];
                y[(size_t)r0 * DIM + n]     = c[mt][nt].x + bv0 + x[(size_t)r0 * DIM + n];
                y[(size_t)r0 * DIM + n + 1] = c[mt][nt].y + bv1 + x[(size_t)r0 * DIM + n + 1];
                y[(size_t)r1 * DIM + n]     = c[mt][nt].z + bv0 + x[(size_t)r1 * DIM + n];
                y[(size_t)r1 * DIM + n + 1] = c[mt][nt].w + bv1 + x[(size_t)r1 * DIM + n + 1];
            }
        }
    }
}

// ---------------- flash attention: 32 Q rows/warp + chunked + 2 CTAs/SM ------
// Block = 256 Q rows, 8 warps; warp w owns rows [w*32, w*32+32) as 2 m-tiles.
// Chunked 16-key pipeline keeps the S live set tiny (4 float4), so regs fit
// the 2-CTAs/SM cap. K/V B-fragments loaded ONCE per chunk, shared by both
// m-tiles -> smem bytes per Q-row halve (crossbar was the binder at m=16).
__global__ __launch_bounds__(256, 2) void flash_bf() {
    __shared__ unsigned Ksw[2][64 * 36];   // [buf][key][dim-pair word]
    __shared__ unsigned Vsp[2][32 * 72];   // [buf][key-pair][dim word]

    const int tid = threadIdx.x, w = tid >> 5, lane = tid & 31;
    const int g = lane >> 2, j = lane & 3;
    const int bh = blockIdx.y;
    const int q0 = blockIdx.x * 256;

    const unsigned* qw = g_qw + ((size_t)bh * SEQ + q0) * HDW;
    const unsigned* kw = g_kw + (size_t)bh * SEQ * HDW;
    const unsigned* vw = g_vw + (size_t)bh * SEQ * HDW;

    // persistent Q fragments for both m-tiles
    unsigned qa[2][4][4];
    #pragma unroll
    for (int mt = 0; mt < 2; mt++) {
        const unsigned* qr  = qw + (size_t)(w * 32 + mt * 16 + g) * HDW;
        const unsigned* qr8 = qr + 8 * HDW;
        #pragma unroll
        for (int kc = 0; kc < 4; kc++) {
            qa[mt][kc][0] = qr [kc * 8 + j];
            qa[mt][kc][1] = qr8[kc * 8 + j];
            qa[mt][kc][2] = qr [kc * 8 + j + 4];
            qa[mt][kc][3] = qr8[kc * 8 + j + 4];
        }
    }

    const int kn  = tid >> 3, kq = (tid & 7) * 4;
    const int kn2 = (tid + 256) >> 3, kq2 = kq;
    const int vp  = tid >> 4, vc = (tid & 15) * 2;
    const int vp2 = (tid + 256) >> 4, vc2 = vc;

#define STAGE(buf, kt) do {                                                     \
    *(uint4*)&Ksw[buf][kn  * 36 + kq ] =                                        \
        *(const uint4*)&kw[(size_t)((kt) + kn ) * HDW + kq ];                   \
    *(uint4*)&Ksw[buf][kn2 * 36 + kq2] =                                        \
        *(const uint4*)&kw[(size_t)((kt) + kn2) * HDW + kq2];                   \
    {                                                                           \
        uint2 w0 = *(const uint2*)&vw[(size_t)((kt) + 2*vp    ) * HDW + vc ];   \
        uint2 w1 = *(const uint2*)&vw[(size_t)((kt) + 2*vp + 1) * HDW + vc ];   \
        uint4 ov;                                                               \
        ov.x = prmt(w0.x, w1.x, 0x5410u); ov.y = prmt(w0.x, w1.x, 0x7632u);     \
        ov.z = prmt(w0.y, w1.y, 0x5410u); ov.w = prmt(w0.y, w1.y, 0x7632u);     \
        *(uint4*)&Vsp[buf][vp * 72 + vc * 2] = ov;                              \
        w0 = *(const uint2*)&vw[(size_t)((kt) + 2*vp2    ) * HDW + vc2];        \
        w1 = *(const uint2*)&vw[(size_t)((kt) + 2*vp2 + 1) * HDW + vc2];        \
        ov.x = prmt(w0.x, w1.x, 0x5410u); ov.y = prmt(w0.x, w1.x, 0x7632u);     \
        ov.z = prmt(w0.y, w1.y, 0x5410u); ov.w = prmt(w0.y, w1.y, 0x7632u);     \
        *(uint4*)&Vsp[buf][vp2 * 72 + vc2 * 2] = ov;                            \
    }                                                                           \
} while (0)

    float4 o[2][8];
    #pragma unroll
    for (int mt = 0; mt < 2; mt++)
        #pragma unroll
        for (int nt = 0; nt < 8; nt++) o[mt][nt] = make_float4(0.f, 0.f, 0.f, 0.f);
    float l0[2] = {0.f, 0.f}, l1[2] = {0.f, 0.f};

    STAGE(0, 0);
    __syncthreads();

    for (int it = 0; it < SEQ / 64; it++) {
        const int cur = it & 1;
        if (it + 1 < SEQ / 64) STAGE(cur ^ 1, (it + 1) * 64);

        // 4 chunks of 16 keys; K/V fragments loaded once, used by both m-tiles
        #pragma unroll
        for (int p = 0; p < 4; p++) {
            float4 c00 = make_float4(0.f, 0.f, 0.f, 0.f);  // mt0, keys 2p*8..
            float4 c01 = make_float4(0.f, 0.f, 0.f, 0.f);  // mt0, keys (2p+1)*8..
            float4 c10 = make_float4(0.f, 0.f, 0.f, 0.f);  // mt1
            float4 c11 = make_float4(0.f, 0.f, 0.f, 0.f);
            const int kb0 = ((2 * p)     * 8 + g) * 36;
            const int kb1 = ((2 * p + 1) * 8 + g) * 36;
            #pragma unroll
            for (int kc = 0; kc < 4; kc++) {
                unsigned b00 = Ksw[cur][kb0 + kc * 8 + j];
                unsigned b01 = Ksw[cur][kb0 + kc * 8 + j + 4];
                unsigned b10 = Ksw[cur][kb1 + kc * 8 + j];
                unsigned b11 = Ksw[cur][kb1 + kc * 8 + j + 4];
                mmabf(c00, qa[0][kc][0], qa[0][kc][1], qa[0][kc][2], qa[0][kc][3], b00, b01);
                mmabf(c10, qa[1][kc][0], qa[1][kc][1], qa[1][kc][2], qa[1][kc][3], b00, b01);
                mmabf(c01, qa[0][kc][0], qa[0][kc][1], qa[0][kc][2], qa[0][kc][3], b10, b11);
                mmabf(c11, qa[1][kc][0], qa[1][kc][1], qa[1][kc][2], qa[1][kc][3], b10, b11);
            }
            // fixed-max softmax
            c00.x = ex2(c00.x - FIXED_MAX); c00.y = ex2(c00.y - FIXED_MAX);
            c00.z = ex2(c00.z - FIXED_MAX); c00.w = ex2(c00.w - FIXED_MAX);
            c01.x = ex2(c01.x - FIXED_MAX); c01.y = ex2(c01.y - FIXED_MAX);
            c01.z = ex2(c01.z - FIXED_MAX); c01.w = ex2(c01.w - FIXED_MAX);
            c10.x = ex2(c10.x - FIXED_MAX); c10.y = ex2(c10.y - FIXED_MAX);
            c10.z = ex2(c10.z - FIXED_MAX); c10.w = ex2(c10.w - FIXED_MAX);
            c11.x = ex2(c11.x - FIXED_MAX); c11.y = ex2(c11.y - FIXED_MAX);
            c11.z = ex2(c11.z - FIXED_MAX); c11.w = ex2(c11.w - FIXED_MAX);
            l0[0] += c00.x + c00.y + c01.x + c01.y;
            l1[0] += c00.z + c00.w + c01.z + c01.w;
            l0[1] += c10.x + c10.y + c11.x + c11.y;
            l1[1] += c10.z + c10.w + c11.z + c11.w;
            unsigned a00 = packbf(c00.x, c00.y);
            unsigned a01 = packbf(c00.z, c00.w);
            unsigned a02 = packbf(c01.x, c01.y);
            unsigned a03 = packbf(c01.z, c01.w);
            unsigned a10 = packbf(c10.x, c10.y);
            unsigned a11 = packbf(c10.z, c10.w);
            unsigned a12 = packbf(c11.x, c11.y);
            unsigned a13 = packbf(c11.z, c11.w);
            const int vb0 = (p * 8 + j) * 72;
            const int vb1 = (p * 8 + j + 4) * 72;
            #pragma unroll
            for (int nt = 0; nt < 8; nt++) {
                unsigned b0 = Vsp[cur][vb0 + nt * 8 + g];
                unsigned b1 = Vsp[cur][vb1 + nt * 8 + g];
                mmabf(o[0][nt], a00, a01, a02, a03, b0, b1);
                mmabf(o[1][nt], a10, a11, a12, a13, b0, b1);
            }
        }
        __syncthreads();
    }

    const int b = bh >> 4, head = bh & 15;
    #pragma unroll
    for (int mt = 0; mt < 2; mt++) {
        float s0 = l0[mt], s1 = l1[mt];
        #pragma unroll
        for (int off = 1; off <= 2; off <<= 1) {
            s0 += __shfl_xor_sync(0xffffffffu, s0, off);
            s1 += __shfl_xor_sync(0xffffffffu, s1, off);
        }
        float inv0 = 1.0f / s0, inv1 = 1.0f / s1;
        size_t row0 = ((size_t)(b * SEQ + q0 + w * 32 + mt * 16 + g)) * DIMW + head * 32;
        size_t row1 = row0 + (size_t)8 * DIMW;
        #pragma unroll
        for (int nt = 0; nt < 8; nt++) {
            g_ow[row0 + nt * 4 + j] = packbf(o[mt][nt].x * inv0, o[mt][nt].y * inv0);
            g_ow[row1 + nt * 4 + j] = packbf(o[mt][nt].z * inv1, o[mt][nt].w * inv1);
        }
    }
#undef STAGE
}

// ---------------- launch -----------------------------------------------------
extern "C" void kernel_launch(void* const* d_in, const int* in_sizes, int n_in,
                              void* d_out, int out_size) {
    const float* x     = (const float*)d_in[0];
    const float* ln_w  = (const float*)d_in[1];
    const float* ln_b  = (const float*)d_in[2];
    const float* qkv_w = (const float*)d_in[3];
    const float* qkv_b = (const float*)d_in[4];
    const float* out_w = (const float*)d_in[5];
    const float* out_b = (const float*)d_in[6];
    float* y = (float*)d_out;

    wconv<<<(N3 * DIMW) / 256, 256>>>(qkv_w, out_w);

    ln_kernel<<<MROWS, 256>>>(x, ln_w, ln_b);

    gemm_bf<0><<<dim3(N3 / 128, MROWS / 128), 256>>>(qkv_b, nullptr, nullptr);

    flash_bf<<<dim3(SEQ / 256, BATCH * NH), 256>>>();

    gemm_bf<1><<<dim3(DIM / 128, MROWS / 128), 256>>>(out_b, x, y);
}

// round 14
// speedup vs baseline: 1.0218x; 1.0218x over previous
#include <cuda_runtime.h>
#include <math.h>
#include <stdint.h>

#define BATCH 4
#define SEQ   2048
#define DIM   1024
#define DIMW  512            // bf16x2 words per row
#define NH    16
#define HD    64
#define HDW   32             // bf16x2 words per head row
#define MROWS (BATCH*SEQ)    // 8192
#define N3    (3*DIM)        // 3072
#define NROWS (BATCH*NH*SEQ) // 131072 head rows

// logit bound in exp2 domain: 8*log2(e) = 11.5416
#define FIXED_MAX 11.6f
#define QSCALE (8.0f * 1.4426950408889634f)

// ---------------- scratch (device globals; referenced ONLY in device code) --
__device__ __align__(16) unsigned g_hw[MROWS * DIMW];        // LN out, bf16x2
__device__ __align__(16) unsigned g_wq[(size_t)N3 * DIMW];   // qkv_w bf16
__device__ __align__(16) unsigned g_wo[(size_t)DIM * DIMW];  // out_w bf16
__device__ __align__(16) unsigned g_qw[(size_t)NROWS * HDW]; // q bf16 [bh][t][dw]
__device__ __align__(16) unsigned g_kw[(size_t)NROWS * HDW];
__device__ __align__(16) unsigned g_vw[(size_t)NROWS * HDW];
__device__ __align__(16) unsigned g_ow[MROWS * DIMW];        // attn out, bf16x2

// ---------------- helpers -----------------------------------------------------
__device__ __forceinline__ unsigned packbf(float lo, float hi) {
    unsigned d;
    asm("cvt.rn.bf16x2.f32 %0, %1, %2;" : "=r"(d) : "f"(hi), "f"(lo));
    return d;
}
__device__ __forceinline__ float ex2(float x) {
    float r;
    asm("ex2.approx.f32 %0, %1;" : "=f"(r) : "f"(x));
    return r;
}
__device__ __forceinline__ unsigned prmt(unsigned a, unsigned b, unsigned s) {
    unsigned d;
    asm("prmt.b32 %0, %1, %2, %3;" : "=r"(d) : "r"(a), "r"(b), "r"(s));
    return d;
}
__device__ __forceinline__ void mmabf(float4& d, unsigned a0, unsigned a1,
                                      unsigned a2, unsigned a3,
                                      unsigned b0, unsigned b1) {
    asm volatile(
        "mma.sync.aligned.m16n8k16.row.col.f32.bf16.bf16.f32 "
        "{%0,%1,%2,%3}, {%4,%5,%6,%7}, {%8,%9}, {%0,%1,%2,%3};\n"
        : "+f"(d.x), "+f"(d.y), "+f"(d.z), "+f"(d.w)
        : "r"(a0), "r"(a1), "r"(a2), "r"(a3), "r"(b0), "r"(b1));
}

// ---------------- weight fp32 -> bf16 conversion (once per call) -------------
__global__ __launch_bounds__(256) void wconv(const float* __restrict__ qkvw,
                                             const float* __restrict__ outw) {
    size_t i = (size_t)blockIdx.x * 256 + threadIdx.x;
    const size_t NQ = (size_t)N3 * DIMW;
    const size_t NO = (size_t)DIM * DIMW;
    if (i < NQ) {
        float2 v = *(const float2*)(qkvw + 2 * i);
        g_wq[i] = packbf(v.x, v.y);
    }
    if (i < NO) {
        float2 v = *(const float2*)(outw + 2 * i);
        g_wo[i] = packbf(v.x, v.y);
    }
}

// ---------------- LayerNorm (fp32 math, bf16 output) ------------------------
__global__ __launch_bounds__(256) void ln_kernel(const float* __restrict__ x,
                                                 const float* __restrict__ w,
                                                 const float* __restrict__ b) {
    int row = blockIdx.x;
    const float4 v = ((const float4*)(x + (size_t)row * DIM))[threadIdx.x];
    float s  = v.x + v.y + v.z + v.w;
    float ss = v.x*v.x + v.y*v.y + v.z*v.z + v.w*v.w;

    __shared__ float sh_s[8], sh_ss[8];
    #pragma unroll
    for (int o = 16; o > 0; o >>= 1) {
        s  += __shfl_xor_sync(0xffffffffu, s,  o);
        ss += __shfl_xor_sync(0xffffffffu, ss, o);
    }
    int wid = threadIdx.x >> 5, lid = threadIdx.x & 31;
    if (lid == 0) { sh_s[wid] = s; sh_ss[wid] = ss; }
    __syncthreads();
    if (wid == 0) {
        s  = (lid < 8) ? sh_s[lid]  : 0.0f;
        ss = (lid < 8) ? sh_ss[lid] : 0.0f;
        #pragma unroll
        for (int o = 4; o > 0; o >>= 1) {
            s  += __shfl_xor_sync(0xffffffffu, s,  o);
            ss += __shfl_xor_sync(0xffffffffu, ss, o);
        }
        if (lid == 0) { sh_s[0] = s; sh_ss[0] = ss; }
    }
    __syncthreads();
    float mean = sh_s[0] * (1.0f / DIM);
    float var  = sh_ss[0] * (1.0f / DIM) - mean * mean;
    float rstd = rsqrtf(var + 1e-5f);

    const float4 wv = ((const float4*)w)[threadIdx.x];
    const float4 bv = ((const float4*)b)[threadIdx.x];
    uint2 out;
    out.x = packbf((v.x - mean) * rstd * wv.x + bv.x,
                   (v.y - mean) * rstd * wv.y + bv.y);
    out.y = packbf((v.z - mean) * rstd * wv.z + bv.z,
                   (v.w - mean) * rstd * wv.w + bv.w);
    *(uint2*)&g_hw[(size_t)row * DIMW + threadIdx.x * 2] = out;
}

// ---------------- bf16 mma.sync GEMM, double-buffered ------------------------
// MODE 0: A=g_hw, B=g_wq, fused bias + per-head L2 norm, bf16 scatter to q/k/v.
// MODE 1: A=g_ow, B=g_wo, y = C + bias + x (fp32).
__device__ __forceinline__ void scatter2(int m, int n, float v0, float v1) {
    int which = n >> 10;
    int hn = n & 1023;
    int head = hn >> 6, d = hn & 63;
    unsigned* dst = (which == 0) ? g_qw : (which == 1) ? g_kw : g_vw;
    int bb = m >> 11, t = m & 2047;
    dst[(((size_t)(bb * NH + head)) * SEQ + t) * HDW + (d >> 1)] = packbf(v0, v1);
}

template<int MODE>
__global__ __launch_bounds__(256) void gemm_bf(const float* __restrict__ bias,
                                               const float* __restrict__ x,
                                               float* __restrict__ y) {
    const unsigned* Asrc = (MODE == 0) ? g_hw : g_ow;
    const unsigned* Bsrc = (MODE == 0) ? g_wq : g_wo;
    __shared__ unsigned Aw[2][128 * 20];
    __shared__ unsigned Bw[2][128 * 20];

    const int tid = threadIdx.x;
    const int w = tid >> 5, lane = tid & 31;
    const int g = lane >> 2, j = lane & 3;
    const int wm = w & 3, wn = w >> 2;
    const int m0 = blockIdx.y * 128;
    const int n0 = blockIdx.x * 128;

    const unsigned* ag = Asrc + (size_t)m0 * DIMW;
    const unsigned* bg = Bsrc + (size_t)n0 * DIMW;
    const int r0l = tid >> 2, q0l = (tid & 3) * 4;
    const int r1l = (tid + 256) >> 2, q1l = q0l;

    float4 c[2][8];
    #pragma unroll
    for (int mt = 0; mt < 2; mt++)
        #pragma unroll
        for (int nt = 0; nt < 8; nt++) c[mt][nt] = make_float4(0.f, 0.f, 0.f, 0.f);

    uint4 pa0, pa1, pb0, pb1;
    pa0 = *(const uint4*)(ag + (size_t)r0l * DIMW + q0l);
    pa1 = *(const uint4*)(ag + (size_t)r1l * DIMW + q1l);
    pb0 = *(const uint4*)(bg + (size_t)r0l * DIMW + q0l);
    pb1 = *(const uint4*)(bg + (size_t)r1l * DIMW + q1l);
    *(uint4*)&Aw[0][r0l * 20 + q0l] = pa0;
    *(uint4*)&Aw[0][r1l * 20 + q1l] = pa1;
    *(uint4*)&Bw[0][r0l * 20 + q0l] = pb0;
    *(uint4*)&Bw[0][r1l * 20 + q1l] = pb1;
    __syncthreads();

    for (int kt = 0; kt < 32; kt++) {
        const int cur = kt & 1, nxt = cur ^ 1;
        if (kt + 1 < 32) {
            int ko = (kt + 1) * 16;
            pa0 = *(const uint4*)(ag + (size_t)r0l * DIMW + ko + q0l);
            pa1 = *(const uint4*)(ag + (size_t)r1l * DIMW + ko + q1l);
            pb0 = *(const uint4*)(bg + (size_t)r0l * DIMW + ko + q0l);
            pb1 = *(const uint4*)(bg + (size_t)r1l * DIMW + ko + q1l);
        }

        #pragma unroll
        for (int kc = 0; kc < 2; kc++) {
            unsigned a[2][4];
            #pragma unroll
            for (int mt = 0; mt < 2; mt++) {
                int row = wm * 32 + mt * 16 + g;
                a[mt][0] = Aw[cur][row * 20 + kc * 8 + j];
                a[mt][1] = Aw[cur][(row + 8) * 20 + kc * 8 + j];
                a[mt][2] = Aw[cur][row * 20 + kc * 8 + j + 4];
                a[mt][3] = Aw[cur][(row + 8) * 20 + kc * 8 + j + 4];
            }
            unsigned b0[8], b1[8];
            #pragma unroll
            for (int nt = 0; nt < 8; nt++) {
                int n = wn * 64 + nt * 8 + g;
                b0[nt] = Bw[cur][n * 20 + kc * 8 + j];
                b1[nt] = Bw[cur][n * 20 + kc * 8 + j + 4];
            }
            #pragma unroll
            for (int mt = 0; mt < 2; mt++)
                #pragma unroll
                for (int nt = 0; nt < 8; nt++)
                    mmabf(c[mt][nt], a[mt][0], a[mt][1], a[mt][2], a[mt][3],
                          b0[nt], b1[nt]);
        }

        if (kt + 1 < 32) {
            *(uint4*)&Aw[nxt][r0l * 20 + q0l] = pa0;
            *(uint4*)&Aw[nxt][r1l * 20 + q1l] = pa1;
            *(uint4*)&Bw[nxt][r0l * 20 + q0l] = pb0;
            *(uint4*)&Bw[nxt][r1l * 20 + q1l] = pb1;
        }
        __syncthreads();
    }

    if (MODE == 0) {
        // warp's 64-col span = exactly one head; lanes 4g+j form the quad
        const int which = (n0 + wn * 64) >> 10;        // 0=q, 1=k, 2=v
        const float sc = (which == 0) ? QSCALE : 1.0f;
        #pragma unroll
        for (int mt = 0; mt < 2; mt++) {
            int r0 = m0 + wm * 32 + mt * 16 + g;
            int r1 = r0 + 8;
            float v0[16], v1[16];
            float ss0 = 0.f, ss1 = 0.f;
            #pragma unroll
            for (int nt = 0; nt < 8; nt++) {
                int n = n0 + wn * 64 + nt * 8 + 2 * j;
                float bv0 = bias[n], bv1 = bias[n + 1];
                v0[2*nt]   = c[mt][nt].x + bv0;
                v0[2*nt+1] = c[mt][nt].y + bv1;
                v1[2*nt]   = c[mt][nt].z + bv0;
                v1[2*nt+1] = c[mt][nt].w + bv1;
                ss0 += v0[2*nt]*v0[2*nt] + v0[2*nt+1]*v0[2*nt+1];
                ss1 += v1[2*nt]*v1[2*nt] + v1[2*nt+1]*v1[2*nt+1];
            }
            float rn0 = 1.f, rn1 = 1.f;
            if (which < 2) {
                #pragma unroll
                for (int off = 1; off <= 2; off <<= 1) {
                    ss0 += __shfl_xor_sync(0xffffffffu, ss0, off);
                    ss1 += __shfl_xor_sync(0xffffffffu, ss1, off);
                }
                rn0 = sc / fmaxf(sqrtf(ss0), 1e-12f);
                rn1 = sc / fmaxf(sqrtf(ss1), 1e-12f);
            }
            #pragma unroll
            for (int nt = 0; nt < 8; nt++) {
                int n = n0 + wn * 64 + nt * 8 + 2 * j;
                scatter2(r0, n, v0[2*nt] * rn0, v0[2*nt+1] * rn0);
                scatter2(r1, n, v1[2*nt] * rn1, v1[2*nt+1] * rn1);
            }
        }
    } else {
        #pragma unroll
        for (int mt = 0; mt < 2; mt++) {
            int r0 = m0 + wm * 32 + mt * 16 + g;
            int r1 = r0 + 8;
            #pragma unroll
            for (int nt = 0; nt < 8; nt++) {
                int n = n0 + wn * 64 + nt * 8 + 2 * j;
                float bv0 = bias[n], bv1 = bias[n + 1];
                y[(size_t)r0 * DIM + n]     = c[mt][nt].x + bv0 + x[(size_t)r0 * DIM + n];
                y[(size_t)r0 * DIM + n + 1] = c[mt][nt].y + bv1 + x[(size_t)r0 * DIM + n + 1];
                y[(size_t)r1 * DIM + n]     = c[mt][nt].z + bv0 + x[(size_t)r1 * DIM + n];
                y[(size_t)r1 * DIM + n + 1] = c[mt][nt].w + bv1 + x[(size_t)r1 * DIM + n + 1];
            }
        }
    }
}

// ---------------- flash attention: m=16/warp, 2 CTAs/SM, split LDG/STS -------
// Chunked 16-key pipeline (small S live set). Global loads for tile t+1 are
// issued at iteration top into REGISTERS; chunk 0's compute (~500 cyc) covers
// the L2 latency; STS into the next buffer happens after chunk 0 — no warp
// ever stalls on a dependent STS right after its LDG (the r11 STAGE bug).
__global__ __launch_bounds__(256, 2) void flash_bf() {
    __shared__ unsigned Ksw[2][64 * 36];   // [buf][key][dim-pair word]
    __shared__ unsigned Vsp[2][32 * 72];   // [buf][key-pair][dim word]

    const int tid = threadIdx.x, w = tid >> 5, lane = tid & 31;
    const int g = lane >> 2, j = lane & 3;
    const int bh = blockIdx.y;
    const int q0 = blockIdx.x * 128;

    const unsigned* qw = g_qw + ((size_t)bh * SEQ + q0) * HDW;
    const unsigned* kw = g_kw + (size_t)bh * SEQ * HDW;
    const unsigned* vw = g_vw + (size_t)bh * SEQ * HDW;

    // persistent Q fragments
    unsigned qa[4][4];
    {
        const unsigned* qr  = qw + (size_t)(w * 16 + g) * HDW;
        const unsigned* qr8 = qr + 8 * HDW;
        #pragma unroll
        for (int kc = 0; kc < 4; kc++) {
            qa[kc][0] = qr [kc * 8 + j];
            qa[kc][1] = qr8[kc * 8 + j];
            qa[kc][2] = qr [kc * 8 + j + 4];
            qa[kc][3] = qr8[kc * 8 + j + 4];
        }
    }

    // staging task indices
    const int kn  = tid >> 3, kq = (tid & 7) * 4;          // K row/word (id=tid)
    const int kn2 = (tid + 256) >> 3;                      // K row (id=tid+256)
    const int vp  = tid >> 4, vc = (tid & 15) * 2;         // V pair/word (id=tid)
    const int vp2 = (tid + 256) >> 4;                      // V pair (id=tid+256)

    float4 o[8];
    #pragma unroll
    for (int nt = 0; nt < 8; nt++) o[nt] = make_float4(0.f, 0.f, 0.f, 0.f);
    float l0 = 0.f, l1 = 0.f;

    // prologue: load + store tile 0 into buffer 0
    {
        uint4 ka = *(const uint4*)&kw[(size_t)kn  * HDW + kq];
        uint4 kb = *(const uint4*)&kw[(size_t)kn2 * HDW + kq];
        uint2 va0 = *(const uint2*)&vw[(size_t)(2*vp     ) * HDW + vc];
        uint2 va1 = *(const uint2*)&vw[(size_t)(2*vp  + 1) * HDW + vc];
        uint2 vb0 = *(const uint2*)&vw[(size_t)(2*vp2    ) * HDW + vc];
        uint2 vb1 = *(const uint2*)&vw[(size_t)(2*vp2 + 1) * HDW + vc];
        *(uint4*)&Ksw[0][kn  * 36 + kq] = ka;
        *(uint4*)&Ksw[0][kn2 * 36 + kq] = kb;
        uint4 ov;
        ov.x = prmt(va0.x, va1.x, 0x5410u); ov.y = prmt(va0.x, va1.x, 0x7632u);
        ov.z = prmt(va0.y, va1.y, 0x5410u); ov.w = prmt(va0.y, va1.y, 0x7632u);
        *(uint4*)&Vsp[0][vp * 72 + vc * 2] = ov;
        ov.x = prmt(vb0.x, vb1.x, 0x5410u); ov.y = prmt(vb0.x, vb1.x, 0x7632u);
        ov.z = prmt(vb0.y, vb1.y, 0x5410u); ov.w = prmt(vb0.y, vb1.y, 0x7632u);
        *(uint4*)&Vsp[0][vp2 * 72 + vc * 2] = ov;
    }
    __syncthreads();

    for (int it = 0; it < SEQ / 64; it++) {
        const int cur = it & 1, nxt = cur ^ 1;
        const bool pf = (it + 1 < SEQ / 64);

        // issue next tile's global loads (registers only; no dependent STS yet)
        uint4 ka, kb; uint2 va0, va1, vb0, vb1;
        if (pf) {
            const int kt = (it + 1) * 64;
            ka  = *(const uint4*)&kw[(size_t)(kt + kn      ) * HDW + kq];
            kb  = *(const uint4*)&kw[(size_t)(kt + kn2     ) * HDW + kq];
            va0 = *(const uint2*)&vw[(size_t)(kt + 2*vp    ) * HDW + vc];
            va1 = *(const uint2*)&vw[(size_t)(kt + 2*vp + 1) * HDW + vc];
            vb0 = *(const uint2*)&vw[(size_t)(kt + 2*vp2    ) * HDW + vc];
            vb1 = *(const uint2*)&vw[(size_t)(kt + 2*vp2 + 1) * HDW + vc];
        }

        // chunks of 16 keys: S -> ex2 -> pack -> PV
        #pragma unroll
        for (int p = 0; p < 4; p++) {
            float4 c0 = make_float4(0.f, 0.f, 0.f, 0.f);
            float4 c1 = make_float4(0.f, 0.f, 0.f, 0.f);
            const int kb0 = ((2 * p)     * 8 + g) * 36;
            const int kb1 = ((2 * p + 1) * 8 + g) * 36;
            #pragma unroll
            for (int kc = 0; kc < 4; kc++) {
                mmabf(c0, qa[kc][0], qa[kc][1], qa[kc][2], qa[kc][3],
                      Ksw[cur][kb0 + kc * 8 + j], Ksw[cur][kb0 + kc * 8 + j + 4]);
                mmabf(c1, qa[kc][0], qa[kc][1], qa[kc][2], qa[kc][3],
                      Ksw[cur][kb1 + kc * 8 + j], Ksw[cur][kb1 + kc * 8 + j + 4]);
            }
            c0.x = ex2(c0.x - FIXED_MAX); c0.y = ex2(c0.y - FIXED_MAX);
            c0.z = ex2(c0.z - FIXED_MAX); c0.w = ex2(c0.w - FIXED_MAX);
            c1.x = ex2(c1.x - FIXED_MAX); c1.y = ex2(c1.y - FIXED_MAX);
            c1.z = ex2(c1.z - FIXED_MAX); c1.w = ex2(c1.w - FIXED_MAX);
            l0 += c0.x + c0.y + c1.x + c1.y;
            l1 += c0.z + c0.w + c1.z + c1.w;
            unsigned a0 = packbf(c0.x, c0.y);
            unsigned a1 = packbf(c0.z, c0.w);
            unsigned a2 = packbf(c1.x, c1.y);
            unsigned a3 = packbf(c1.z, c1.w);
            const int vbo0 = (p * 8 + j) * 72;
            const int vbo1 = (p * 8 + j + 4) * 72;
            #pragma unroll
            for (int nt = 0; nt < 8; nt++) {
                mmabf(o[nt], a0, a1, a2, a3,
                      Vsp[cur][vbo0 + nt * 8 + g], Vsp[cur][vbo1 + nt * 8 + g]);
            }

            // after chunk 0 (~500 cyc in): store staged tile into next buffer
            if (p == 0 && pf) {
                *(uint4*)&Ksw[nxt][kn  * 36 + kq] = ka;
                *(uint4*)&Ksw[nxt][kn2 * 36 + kq] = kb;
                uint4 ov;
                ov.x = prmt(va0.x, va1.x, 0x5410u); ov.y = prmt(va0.x, va1.x, 0x7632u);
                ov.z = prmt(va0.y, va1.y, 0x5410u); ov.w = prmt(va0.y, va1.y, 0x7632u);
                *(uint4*)&Vsp[nxt][vp * 72 + vc * 2] = ov;
                ov.x = prmt(vb0.x, vb1.x, 0x5410u); ov.y = prmt(vb0.x, vb1.x, 0x7632u);
                ov.z = prmt(vb0.y, vb1.y, 0x5410u); ov.w = prmt(vb0.y, vb1.y, 0x7632u);
                *(uint4*)&Vsp[nxt][vp2 * 72 + vc * 2] = ov;
            }
        }
        __syncthreads();
    }

    // one l reduction for the whole kernel (quad lanes share a row)
    #pragma unroll
    for (int off = 1; off <= 2; off <<= 1) {
        l0 += __shfl_xor_sync(0xffffffffu, l0, off);
        l1 += __shfl_xor_sync(0xffffffffu, l1, off);
    }
    float inv0 = 1.0f / l0, inv1 = 1.0f / l1;

    const int b = bh >> 4, head = bh & 15;
    size_t row0 = ((size_t)(b * SEQ + q0 + w * 16 + g)) * DIMW + head * 32;
    size_t row1 = row0 + (size_t)8 * DIMW;
    #pragma unroll
    for (int nt = 0; nt < 8; nt++) {
        g_ow[row0 + nt * 4 + j] = packbf(o[nt].x * inv0, o[nt].y * inv0);
        g_ow[row1 + nt * 4 + j] = packbf(o[nt].z * inv1, o[nt].w * inv1);
    }
}

// ---------------- launch -----------------------------------------------------
extern "C" void kernel_launch(void* const* d_in, const int* in_sizes, int n_in,
                              void* d_out, int out_size) {
    const float* x     = (const float*)d_in[0];
    const float* ln_w  = (const float*)d_in[1];
    const float* ln_b  = (const float*)d_in[2];
    const float* qkv_w = (const float*)d_in[3];
    const float* qkv_b = (const float*)d_in[4];
    const float* out_w = (const float*)d_in[5];
    const float* out_b = (const float*)d_in[6];
    float* y = (float*)d_out;

    wconv<<<(N3 * DIMW) / 256, 256>>>(qkv_w, out_w);

    ln_kernel<<<MROWS, 256>>>(x, ln_w, ln_b);

    gemm_bf<0><<<dim3(N3 / 128, MROWS / 128), 256>>>(qkv_b, nullptr, nullptr);

    flash_bf<<<dim3(SEQ / 128, BATCH * NH), 256>>>();

    gemm_bf<1><<<dim3(DIM / 128, MROWS / 128), 256>>>(out_b, x, y);
}

// round 15
// speedup vs baseline: 1.0438x; 1.0216x over previous
#include <cuda_runtime.h>
#include <cuda_fp16.h>
#include <math.h>
#include <stdint.h>

#define BATCH 4
#define SEQ   2048
#define DIM   1024
#define DIMW  512            // 16-bit-pair words per row
#define NH    16
#define HD    64
#define HDW   32             // 16-bit-pair words per head row
#define MROWS (BATCH*SEQ)    // 8192
#define N3    (3*DIM)        // 3072
#define NROWS (BATCH*NH*SEQ) // 131072 head rows

// logit bound in exp2 domain: 8*log2(e) = 11.5416
#define FIXED_MAX 11.6f
#define QSCALE (8.0f * 1.4426950408889634f)

// ---------------- scratch (device globals; referenced ONLY in device code) --
__device__ __align__(16) unsigned g_hw[MROWS * DIMW];        // LN out, bf16x2
__device__ __align__(16) unsigned g_wq[(size_t)N3 * DIMW];   // qkv_w bf16
__device__ __align__(16) unsigned g_wo[(size_t)DIM * DIMW];  // out_w bf16
__device__ __align__(16) unsigned g_qw[(size_t)NROWS * HDW]; // q f16 [bh][t][dw]
__device__ __align__(16) unsigned g_kw[(size_t)NROWS * HDW]; // k f16
__device__ __align__(16) unsigned g_vw[(size_t)NROWS * HDW]; // v f16
__device__ __align__(16) unsigned g_ow[MROWS * DIMW];        // attn out, bf16x2

// ---------------- helpers -----------------------------------------------------
__device__ __forceinline__ unsigned packbf(float lo, float hi) {
    unsigned d;
    asm("cvt.rn.bf16x2.f32 %0, %1, %2;" : "=r"(d) : "f"(hi), "f"(lo));
    return d;
}
__device__ __forceinline__ unsigned packf16(float lo, float hi) {
    __half2 h = __floats2half2_rn(lo, hi);
    return *reinterpret_cast<unsigned*>(&h);
}
__device__ __forceinline__ float ex2(float x) {
    float r;
    asm("ex2.approx.f32 %0, %1;" : "=f"(r) : "f"(x));
    return r;
}
__device__ __forceinline__ unsigned prmt(unsigned a, unsigned b, unsigned s) {
    unsigned d;
    asm("prmt.b32 %0, %1, %2, %3;" : "=r"(d) : "r"(a), "r"(b), "r"(s));
    return d;
}
// bf16 in, f32 acc (GEMM)
__device__ __forceinline__ void mmabf(float4& d, unsigned a0, unsigned a1,
                                      unsigned a2, unsigned a3,
                                      unsigned b0, unsigned b1) {
    asm volatile(
        "mma.sync.aligned.m16n8k16.row.col.f32.bf16.bf16.f32 "
        "{%0,%1,%2,%3}, {%4,%5,%6,%7}, {%8,%9}, {%0,%1,%2,%3};\n"
        : "+f"(d.x), "+f"(d.y), "+f"(d.z), "+f"(d.w)
        : "r"(a0), "r"(a1), "r"(a2), "r"(a3), "r"(b0), "r"(b1));
}
// f16 in, f32 acc (flash S)
__device__ __forceinline__ void mmaf16s(float4& d, unsigned a0, unsigned a1,
                                        unsigned a2, unsigned a3,
                                        unsigned b0, unsigned b1) {
    asm volatile(
        "mma.sync.aligned.m16n8k16.row.col.f32.f16.f16.f32 "
        "{%0,%1,%2,%3}, {%4,%5,%6,%7}, {%8,%9}, {%0,%1,%2,%3};\n"
        : "+f"(d.x), "+f"(d.y), "+f"(d.z), "+f"(d.w)
        : "r"(a0), "r"(a1), "r"(a2), "r"(a3), "r"(b0), "r"(b1));
}
// f16 in, f16 acc (flash PV; D/C are 2 packed f16x2 regs)
__device__ __forceinline__ void mmaf16a(unsigned& d0, unsigned& d1,
                                        unsigned a0, unsigned a1,
                                        unsigned a2, unsigned a3,
                                        unsigned b0, unsigned b1) {
    asm volatile(
        "mma.sync.aligned.m16n8k16.row.col.f16.f16.f16.f16 "
        "{%0,%1}, {%2,%3,%4,%5}, {%6,%7}, {%0,%1};\n"
        : "+r"(d0), "+r"(d1)
        : "r"(a0), "r"(a1), "r"(a2), "r"(a3), "r"(b0), "r"(b1));
}

// ---------------- weight fp32 -> bf16 conversion (once per call) -------------
__global__ __launch_bounds__(256) void wconv(const float* __restrict__ qkvw,
                                             const float* __restrict__ outw) {
    size_t i = (size_t)blockIdx.x * 256 + threadIdx.x;
    const size_t NQ = (size_t)N3 * DIMW;
    const size_t NO = (size_t)DIM * DIMW;
    if (i < NQ) {
        float2 v = *(const float2*)(qkvw + 2 * i);
        g_wq[i] = packbf(v.x, v.y);
    }
    if (i < NO) {
        float2 v = *(const float2*)(outw + 2 * i);
        g_wo[i] = packbf(v.x, v.y);
    }
}

// ---------------- LayerNorm (fp32 math, bf16 output) ------------------------
__global__ __launch_bounds__(256) void ln_kernel(const float* __restrict__ x,
                                                 const float* __restrict__ w,
                                                 const float* __restrict__ b) {
    int row = blockIdx.x;
    const float4 v = ((const float4*)(x + (size_t)row * DIM))[threadIdx.x];
    float s  = v.x + v.y + v.z + v.w;
    float ss = v.x*v.x + v.y*v.y + v.z*v.z + v.w*v.w;

    __shared__ float sh_s[8], sh_ss[8];
    #pragma unroll
    for (int o = 16; o > 0; o >>= 1) {
        s  += __shfl_xor_sync(0xffffffffu, s,  o);
        ss += __shfl_xor_sync(0xffffffffu, ss, o);
    }
    int wid = threadIdx.x >> 5, lid = threadIdx.x & 31;
    if (lid == 0) { sh_s[wid] = s; sh_ss[wid] = ss; }
    __syncthreads();
    if (wid == 0) {
        s  = (lid < 8) ? sh_s[lid]  : 0.0f;
        ss = (lid < 8) ? sh_ss[lid] : 0.0f;
        #pragma unroll
        for (int o = 4; o > 0; o >>= 1) {
            s  += __shfl_xor_sync(0xffffffffu, s,  o);
            ss += __shfl_xor_sync(0xffffffffu, ss, o);
        }
        if (lid == 0) { sh_s[0] = s; sh_ss[0] = ss; }
    }
    __syncthreads();
    float mean = sh_s[0] * (1.0f / DIM);
    float var  = sh_ss[0] * (1.0f / DIM) - mean * mean;
    float rstd = rsqrtf(var + 1e-5f);

    const float4 wv = ((const float4*)w)[threadIdx.x];
    const float4 bv = ((const float4*)b)[threadIdx.x];
    uint2 out;
    out.x = packbf((v.x - mean) * rstd * wv.x + bv.x,
                   (v.y - mean) * rstd * wv.y + bv.y);
    out.y = packbf((v.z - mean) * rstd * wv.z + bv.z,
                   (v.w - mean) * rstd * wv.w + bv.w);
    *(uint2*)&g_hw[(size_t)row * DIMW + threadIdx.x * 2] = out;
}

// ---------------- bf16 mma.sync GEMM, double-buffered ------------------------
// MODE 0: A=g_hw, B=g_wq, fused bias + per-head L2 norm, f16 scatter to q/k/v.
// MODE 1: A=g_ow, B=g_wo, y = C + bias + x (fp32).
__device__ __forceinline__ void scatter2(int m, int n, float v0, float v1) {
    int which = n >> 10;
    int hn = n & 1023;
    int head = hn >> 6, d = hn & 63;
    unsigned* dst = (which == 0) ? g_qw : (which == 1) ? g_kw : g_vw;
    int bb = m >> 11, t = m & 2047;
    dst[(((size_t)(bb * NH + head)) * SEQ + t) * HDW + (d >> 1)] = packf16(v0, v1);
}

template<int MODE>
__global__ __launch_bounds__(256) void gemm_bf(const float* __restrict__ bias,
                                               const float* __restrict__ x,
                                               float* __restrict__ y) {
    const unsigned* Asrc = (MODE == 0) ? g_hw : g_ow;
    const unsigned* Bsrc = (MODE == 0) ? g_wq : g_wo;
    __shared__ unsigned Aw[2][128 * 20];
    __shared__ unsigned Bw[2][128 * 20];

    const int tid = threadIdx.x;
    const int w = tid >> 5, lane = tid & 31;
    const int g = lane >> 2, j = lane & 3;
    const int wm = w & 3, wn = w >> 2;
    const int m0 = blockIdx.y * 128;
    const int n0 = blockIdx.x * 128;

    const unsigned* ag = Asrc + (size_t)m0 * DIMW;
    const unsigned* bg = Bsrc + (size_t)n0 * DIMW;
    const int r0l = tid >> 2, q0l = (tid & 3) * 4;
    const int r1l = (tid + 256) >> 2, q1l = q0l;

    float4 c[2][8];
    #pragma unroll
    for (int mt = 0; mt < 2; mt++)
        #pragma unroll
        for (int nt = 0; nt < 8; nt++) c[mt][nt] = make_float4(0.f, 0.f, 0.f, 0.f);

    uint4 pa0, pa1, pb0, pb1;
    pa0 = *(const uint4*)(ag + (size_t)r0l * DIMW + q0l);
    pa1 = *(const uint4*)(ag + (size_t)r1l * DIMW + q1l);
    pb0 = *(const uint4*)(bg + (size_t)r0l * DIMW + q0l);
    pb1 = *(const uint4*)(bg + (size_t)r1l * DIMW + q1l);
    *(uint4*)&Aw[0][r0l * 20 + q0l] = pa0;
    *(uint4*)&Aw[0][r1l * 20 + q1l] = pa1;
    *(uint4*)&Bw[0][r0l * 20 + q0l] = pb0;
    *(uint4*)&Bw[0][r1l * 20 + q1l] = pb1;
    __syncthreads();

    for (int kt = 0; kt < 32; kt++) {
        const int cur = kt & 1, nxt = cur ^ 1;
        if (kt + 1 < 32) {
            int ko = (kt + 1) * 16;
            pa0 = *(const uint4*)(ag + (size_t)r0l * DIMW + ko + q0l);
            pa1 = *(const uint4*)(ag + (size_t)r1l * DIMW + ko + q1l);
            pb0 = *(const uint4*)(bg + (size_t)r0l * DIMW + ko + q0l);
            pb1 = *(const uint4*)(bg + (size_t)r1l * DIMW + ko + q1l);
        }

        #pragma unroll
        for (int kc = 0; kc < 2; kc++) {
            unsigned a[2][4];
            #pragma unroll
            for (int mt = 0; mt < 2; mt++) {
                int row = wm * 32 + mt * 16 + g;
                a[mt][0] = Aw[cur][row * 20 + kc * 8 + j];
                a[mt][1] = Aw[cur][(row + 8) * 20 + kc * 8 + j];
                a[mt][2] = Aw[cur][row * 20 + kc * 8 + j + 4];
                a[mt][3] = Aw[cur][(row + 8) * 20 + kc * 8 + j + 4];
            }
            unsigned b0[8], b1[8];
            #pragma unroll
            for (int nt = 0; nt < 8; nt++) {
                int n = wn * 64 + nt * 8 + g;
                b0[nt] = Bw[cur][n * 20 + kc * 8 + j];
                b1[nt] = Bw[cur][n * 20 + kc * 8 + j + 4];
            }
            #pragma unroll
            for (int mt = 0; mt < 2; mt++)
                #pragma unroll
                for (int nt = 0; nt < 8; nt++)
                    mmabf(c[mt][nt], a[mt][0], a[mt][1], a[mt][2], a[mt][3],
                          b0[nt], b1[nt]);
        }

        if (kt + 1 < 32) {
            *(uint4*)&Aw[nxt][r0l * 20 + q0l] = pa0;
            *(uint4*)&Aw[nxt][r1l * 20 + q1l] = pa1;
            *(uint4*)&Bw[nxt][r0l * 20 + q0l] = pb0;
            *(uint4*)&Bw[nxt][r1l * 20 + q1l] = pb1;
        }
        __syncthreads();
    }

    if (MODE == 0) {
        // warp's 64-col span = exactly one head; lanes 4g+j form the quad
        const int which = (n0 + wn * 64) >> 10;        // 0=q, 1=k, 2=v
        const float sc = (which == 0) ? QSCALE : 1.0f;
        #pragma unroll
        for (int mt = 0; mt < 2; mt++) {
            int r0 = m0 + wm * 32 + mt * 16 + g;
            int r1 = r0 + 8;
            float v0[16], v1[16];
            float ss0 = 0.f, ss1 = 0.f;
            #pragma unroll
            for (int nt = 0; nt < 8; nt++) {
                int n = n0 + wn * 64 + nt * 8 + 2 * j;
                float bv0 = bias[n], bv1 = bias[n + 1];
                v0[2*nt]   = c[mt][nt].x + bv0;
                v0[2*nt+1] = c[mt][nt].y + bv1;
                v1[2*nt]   = c[mt][nt].z + bv0;
                v1[2*nt+1] = c[mt][nt].w + bv1;
                ss0 += v0[2*nt]*v0[2*nt] + v0[2*nt+1]*v0[2*nt+1];
                ss1 += v1[2*nt]*v1[2*nt] + v1[2*nt+1]*v1[2*nt+1];
            }
            float rn0 = 1.f, rn1 = 1.f;
            if (which < 2) {
                #pragma unroll
                for (int off = 1; off <= 2; off <<= 1) {
                    ss0 += __shfl_xor_sync(0xffffffffu, ss0, off);
                    ss1 += __shfl_xor_sync(0xffffffffu, ss1, off);
                }
                rn0 = sc / fmaxf(sqrtf(ss0), 1e-12f);
                rn1 = sc / fmaxf(sqrtf(ss1), 1e-12f);
            }
            #pragma unroll
            for (int nt = 0; nt < 8; nt++) {
                int n = n0 + wn * 64 + nt * 8 + 2 * j;
                scatter2(r0, n, v0[2*nt] * rn0, v0[2*nt+1] * rn0);
                scatter2(r1, n, v1[2*nt] * rn1, v1[2*nt+1] * rn1);
            }
        }
    } else {
        #pragma unroll
        for (int mt = 0; mt < 2; mt++) {
            int r0 = m0 + wm * 32 + mt * 16 + g;
            int r1 = r0 + 8;
            #pragma unroll
            for (int nt = 0; nt < 8; nt++) {
                int n = n0 + wn * 64 + nt * 8 + 2 * j;
                float bv0 = bias[n], bv1 = bias[n + 1];
                y[(size_t)r0 * DIM + n]     = c[mt][nt].x + bv0 + x[(size_t)r0 * DIM + n];
                y[(size_t)r0 * DIM + n + 1] = c[mt][nt].y + bv1 + x[(size_t)r0 * DIM + n + 1];
                y[(size_t)r1 * DIM + n]     = c[mt][nt].z + bv0 + x[(size_t)r1 * DIM + n];
                y[(size_t)r1 * DIM + n + 1] = c[mt][nt].w + bv1 + x[(size_t)r1 * DIM + n + 1];
            }
        }
    }
}

// ---------------- flash attention: m=32/warp, f16, chunked, 2 CTAs/SM --------
// Block = 256 Q rows, 8 warps; warp w owns rows [w*32, w*32+32) as 2 m-tiles.
// fp16 datapath: S mma f16->f32; PV mma f16->f16 accum (O = 32 regs, not 64).
// K/V fragments loaded once per chunk and shared by both m-tiles: smem bytes
// per Q-row halve vs m=16 (the crossbar was the binder). r11 inline staging.
__global__ __launch_bounds__(256, 2) void flash_bf() {
    __shared__ unsigned Ksw[2][64 * 36];   // [buf][key][dim-pair word]
    __shared__ unsigned Vsp[2][32 * 72];   // [buf][key-pair][dim word]

    const int tid = threadIdx.x, w = tid >> 5, lane = tid & 31;
    const int g = lane >> 2, j = lane & 3;
    const int bh = blockIdx.y;
    const int q0 = blockIdx.x * 256;

    const unsigned* qw = g_qw + ((size_t)bh * SEQ + q0) * HDW;
    const unsigned* kw = g_kw + (size_t)bh * SEQ * HDW;
    const unsigned* vw = g_vw + (size_t)bh * SEQ * HDW;

    // persistent Q fragments for both m-tiles (f16x2 words)
    unsigned qa[2][4][4];
    #pragma unroll
    for (int mt = 0; mt < 2; mt++) {
        const unsigned* qr  = qw + (size_t)(w * 32 + mt * 16 + g) * HDW;
        const unsigned* qr8 = qr + 8 * HDW;
        #pragma unroll
        for (int kc = 0; kc < 4; kc++) {
            qa[mt][kc][0] = qr [kc * 8 + j];
            qa[mt][kc][1] = qr8[kc * 8 + j];
            qa[mt][kc][2] = qr [kc * 8 + j + 4];
            qa[mt][kc][3] = qr8[kc * 8 + j + 4];
        }
    }

    const int kn  = tid >> 3, kq = (tid & 7) * 4;
    const int kn2 = (tid + 256) >> 3, kq2 = kq;
    const int vp  = tid >> 4, vc = (tid & 15) * 2;
    const int vp2 = (tid + 256) >> 4, vc2 = vc;

#define STAGE(buf, kt) do {                                                     \
    *(uint4*)&Ksw[buf][kn  * 36 + kq ] =                                        \
        *(const uint4*)&kw[(size_t)((kt) + kn ) * HDW + kq ];                   \
    *(uint4*)&Ksw[buf][kn2 * 36 + kq2] =                                        \
        *(const uint4*)&kw[(size_t)((kt) + kn2) * HDW + kq2];                   \
    {                                                                           \
        uint2 w0 = *(const uint2*)&vw[(size_t)((kt) + 2*vp    ) * HDW + vc ];   \
        uint2 w1 = *(const uint2*)&vw[(size_t)((kt) + 2*vp + 1) * HDW + vc ];   \
        uint4 ov;                                                               \
        ov.x = prmt(w0.x, w1.x, 0x5410u); ov.y = prmt(w0.x, w1.x, 0x7632u);     \
        ov.z = prmt(w0.y, w1.y, 0x5410u); ov.w = prmt(w0.y, w1.y, 0x7632u);     \
        *(uint4*)&Vsp[buf][vp * 72 + vc * 2] = ov;                              \
        w0 = *(const uint2*)&vw[(size_t)((kt) + 2*vp2    ) * HDW + vc2];        \
        w1 = *(const uint2*)&vw[(size_t)((kt) + 2*vp2 + 1) * HDW + vc2];        \
        ov.x = prmt(w0.x, w1.x, 0x5410u); ov.y = prmt(w0.x, w1.x, 0x7632u);     \
        ov.z = prmt(w0.y, w1.y, 0x5410u); ov.w = prmt(w0.y, w1.y, 0x7632u);     \
        *(uint4*)&Vsp[buf][vp2 * 72 + vc2 * 2] = ov;                            \
    }                                                                           \
} while (0)

    // O accumulators in f16x2: [mt][nt] -> 2 packed regs each
    unsigned o0[2][8], o1[2][8];
    #pragma unroll
    for (int mt = 0; mt < 2; mt++)
        #pragma unroll
        for (int nt = 0; nt < 8; nt++) { o0[mt][nt] = 0u; o1[mt][nt] = 0u; }
    float l0[2] = {0.f, 0.f}, l1[2] = {0.f, 0.f};

    STAGE(0, 0);
    __syncthreads();

    for (int it = 0; it < SEQ / 64; it++) {
        const int cur = it & 1;
        if (it + 1 < SEQ / 64) STAGE(cur ^ 1, (it + 1) * 64);

        // 4 chunks of 16 keys; K/V fragments loaded once, used by both m-tiles
        #pragma unroll
        for (int p = 0; p < 4; p++) {
            float4 c00 = make_float4(0.f, 0.f, 0.f, 0.f);
            float4 c01 = make_float4(0.f, 0.f, 0.f, 0.f);
            float4 c10 = make_float4(0.f, 0.f, 0.f, 0.f);
            float4 c11 = make_float4(0.f, 0.f, 0.f, 0.f);
            const int kb0 = ((2 * p)     * 8 + g) * 36;
            const int kb1 = ((2 * p + 1) * 8 + g) * 36;
            #pragma unroll
            for (int kc = 0; kc < 4; kc++) {
                unsigned b00 = Ksw[cur][kb0 + kc * 8 + j];
                unsigned b01 = Ksw[cur][kb0 + kc * 8 + j + 4];
                unsigned b10 = Ksw[cur][kb1 + kc * 8 + j];
                unsigned b11 = Ksw[cur][kb1 + kc * 8 + j + 4];
                mmaf16s(c00, qa[0][kc][0], qa[0][kc][1], qa[0][kc][2], qa[0][kc][3], b00, b01);
                mmaf16s(c10, qa[1][kc][0], qa[1][kc][1], qa[1][kc][2], qa[1][kc][3], b00, b01);
                mmaf16s(c01, qa[0][kc][0], qa[0][kc][1], qa[0][kc][2], qa[0][kc][3], b10, b11);
                mmaf16s(c11, qa[1][kc][0], qa[1][kc][1], qa[1][kc][2], qa[1][kc][3], b10, b11);
            }
            // fixed-max softmax (exp2 domain)
            c00.x = ex2(c00.x - FIXED_MAX); c00.y = ex2(c00.y - FIXED_MAX);
            c00.z = ex2(c00.z - FIXED_MAX); c00.w = ex2(c00.w - FIXED_MAX);
            c01.x = ex2(c01.x - FIXED_MAX); c01.y = ex2(c01.y - FIXED_MAX);
            c01.z = ex2(c01.z - FIXED_MAX); c01.w = ex2(c01.w - FIXED_MAX);
            c10.x = ex2(c10.x - FIXED_MAX); c10.y = ex2(c10.y - FIXED_MAX);
            c10.z = ex2(c10.z - FIXED_MAX); c10.w = ex2(c10.w - FIXED_MAX);
            c11.x = ex2(c11.x - FIXED_MAX); c11.y = ex2(c11.y - FIXED_MAX);
            c11.z = ex2(c11.z - FIXED_MAX); c11.w = ex2(c11.w - FIXED_MAX);
            l0[0] += c00.x + c00.y + c01.x + c01.y;
            l1[0] += c00.z + c00.w + c01.z + c01.w;
            l0[1] += c10.x + c10.y + c11.x + c11.y;
            l1[1] += c10.z + c10.w + c11.z + c11.w;
            unsigned a00 = packf16(c00.x, c00.y);
            unsigned a01 = packf16(c00.z, c00.w);
            unsigned a02 = packf16(c01.x, c01.y);
            unsigned a03 = packf16(c01.z, c01.w);
            unsigned a10 = packf16(c10.x, c10.y);
            unsigned a11 = packf16(c10.z, c10.w);
            unsigned a12 = packf16(c11.x, c11.y);
            unsigned a13 = packf16(c11.z, c11.w);
            const int vb0 = (p * 8 + j) * 72;
            const int vb1 = (p * 8 + j + 4) * 72;
            #pragma unroll
            for (int nt = 0; nt < 8; nt++) {
                unsigned b0 = Vsp[cur][vb0 + nt * 8 + g];
                unsigned b1 = Vsp[cur][vb1 + nt * 8 + g];
                mmaf16a(o0[0][nt], o1[0][nt], a00, a01, a02, a03, b0, b1);
                mmaf16a(o0[1][nt], o1[1][nt], a10, a11, a12, a13, b0, b1);
            }
        }
        __syncthreads();
    }

    const int b = bh >> 4, head = bh & 15;
    #pragma unroll
    for (int mt = 0; mt < 2; mt++) {
        float s0 = l0[mt], s1 = l1[mt];
        #pragma unroll
        for (int off = 1; off <= 2; off <<= 1) {
            s0 += __shfl_xor_sync(0xffffffffu, s0, off);
            s1 += __shfl_xor_sync(0xffffffffu, s1, off);
        }
        float inv0 = 1.0f / s0, inv1 = 1.0f / s1;
        size_t row0 = ((size_t)(b * SEQ + q0 + w * 32 + mt * 16 + g)) * DIMW + head * 32;
        size_t row1 = row0 + (size_t)8 * DIMW;
        #pragma unroll
        for (int nt = 0; nt < 8; nt++) {
            float2 f0 = __half22float2(*reinterpret_cast<__half2*>(&o0[mt][nt]));
            float2 f1 = __half22float2(*reinterpret_cast<__half2*>(&o1[mt][nt]));
            g_ow[row0 + nt * 4 + j] = packbf(f0.x * inv0, f0.y * inv0);
            g_ow[row1 + nt * 4 + j] = packbf(f1.x * inv1, f1.y * inv1);
        }
    }
#undef STAGE
}

// ---------------- launch -----------------------------------------------------
extern "C" void kernel_launch(void* const* d_in, const int* in_sizes, int n_in,
                              void* d_out, int out_size) {
    const float* x     = (const float*)d_in[0];
    const float* ln_w  = (const float*)d_in[1];
    const float* ln_b  = (const float*)d_in[2];
    const float* qkv_w = (const float*)d_in[3];
    const float* qkv_b = (const float*)d_in[4];
    const float* out_w = (const float*)d_in[5];
    const float* out_b = (const float*)d_in[6];
    float* y = (float*)d_out;

    wconv<<<(N3 * DIMW) / 256, 256>>>(qkv_w, out_w);

    ln_kernel<<<MROWS, 256>>>(x, ln_w, ln_b);

    gemm_bf<0><<<dim3(N3 / 128, MROWS / 128), 256>>>(qkv_b, nullptr, nullptr);

    flash_bf<<<dim3(SEQ / 256, BATCH * NH), 256>>>();

    gemm_bf<1><<<dim3(DIM / 128, MROWS / 128), 256>>>(out_b, x, y);
}

// round 16
// speedup vs baseline: 1.1197x; 1.0726x over previous
#include <cuda_runtime.h>
#include <cuda_fp16.h>
#include <math.h>
#include <stdint.h>

#define BATCH 4
#define SEQ   2048
#define DIM   1024
#define DIMW  512            // 16-bit-pair words per row
#define NH    16
#define HD    64
#define HDW   32             // 16-bit-pair words per head row
#define MROWS (BATCH*SEQ)    // 8192
#define N3    (3*DIM)        // 3072
#define NROWS (BATCH*NH*SEQ) // 131072 head rows

// logit bound in exp2 domain: 8*log2(e) = 11.5416
#define FIXED_MAX 11.6f
#define QSCALE (8.0f * 1.4426950408889634f)

// ---------------- scratch (device globals; referenced ONLY in device code) --
__device__ __align__(16) unsigned g_hw[MROWS * DIMW];        // LN out, bf16x2
__device__ __align__(16) unsigned g_wq[(size_t)N3 * DIMW];   // qkv_w bf16
__device__ __align__(16) unsigned g_wo[(size_t)DIM * DIMW];  // out_w bf16
__device__ __align__(16) unsigned g_qw[(size_t)NROWS * HDW]; // q f16 [bh][t][dw]
__device__ __align__(16) unsigned g_kw[(size_t)NROWS * HDW]; // k f16
__device__ __align__(16) unsigned g_vw[(size_t)NROWS * HDW]; // v f16
__device__ __align__(16) unsigned g_ow[MROWS * DIMW];        // attn out, bf16x2

// ---------------- helpers -----------------------------------------------------
__device__ __forceinline__ unsigned packbf(float lo, float hi) {
    unsigned d;
    asm("cvt.rn.bf16x2.f32 %0, %1, %2;" : "=r"(d) : "f"(hi), "f"(lo));
    return d;
}
__device__ __forceinline__ unsigned packf16(float lo, float hi) {
    __half2 h = __floats2half2_rn(lo, hi);
    return *reinterpret_cast<unsigned*>(&h);
}
__device__ __forceinline__ float ex2(float x) {
    float r;
    asm("ex2.approx.f32 %0, %1;" : "=f"(r) : "f"(x));
    return r;
}
__device__ __forceinline__ unsigned prmt(unsigned a, unsigned b, unsigned s) {
    unsigned d;
    asm("prmt.b32 %0, %1, %2, %3;" : "=r"(d) : "r"(a), "r"(b), "r"(s));
    return d;
}
// bf16 in, f32 acc (GEMM)
__device__ __forceinline__ void mmabf(float4& d, unsigned a0, unsigned a1,
                                      unsigned a2, unsigned a3,
                                      unsigned b0, unsigned b1) {
    asm volatile(
        "mma.sync.aligned.m16n8k16.row.col.f32.bf16.bf16.f32 "
        "{%0,%1,%2,%3}, {%4,%5,%6,%7}, {%8,%9}, {%0,%1,%2,%3};\n"
        : "+f"(d.x), "+f"(d.y), "+f"(d.z), "+f"(d.w)
        : "r"(a0), "r"(a1), "r"(a2), "r"(a3), "r"(b0), "r"(b1));
}
// f16 in, f32 acc (flash S)
__device__ __forceinline__ void mmaf16s(float4& d, unsigned a0, unsigned a1,
                                        unsigned a2, unsigned a3,
                                        unsigned b0, unsigned b1) {
    asm volatile(
        "mma.sync.aligned.m16n8k16.row.col.f32.f16.f16.f32 "
        "{%0,%1,%2,%3}, {%4,%5,%6,%7}, {%8,%9}, {%0,%1,%2,%3};\n"
        : "+f"(d.x), "+f"(d.y), "+f"(d.z), "+f"(d.w)
        : "r"(a0), "r"(a1), "r"(a2), "r"(a3), "r"(b0), "r"(b1));
}
// f16 in, f16 acc (flash PV; D/C are 2 packed f16x2 regs)
__device__ __forceinline__ void mmaf16a(unsigned& d0, unsigned& d1,
                                        unsigned a0, unsigned a1,
                                        unsigned a2, unsigned a3,
                                        unsigned b0, unsigned b1) {
    asm volatile(
        "mma.sync.aligned.m16n8k16.row.col.f16.f16.f16.f16 "
        "{%0,%1}, {%2,%3,%4,%5}, {%6,%7}, {%0,%1};\n"
        : "+r"(d0), "+r"(d1)
        : "r"(a0), "r"(a1), "r"(a2), "r"(a3), "r"(b0), "r"(b1));
}

// ---------------- weight fp32 -> bf16 conversion (once per call) -------------
__global__ __launch_bounds__(256) void wconv(const float* __restrict__ qkvw,
                                             const float* __restrict__ outw) {
    size_t i = (size_t)blockIdx.x * 256 + threadIdx.x;
    const size_t NQ = (size_t)N3 * DIMW;
    const size_t NO = (size_t)DIM * DIMW;
    if (i < NQ) {
        float2 v = *(const float2*)(qkvw + 2 * i);
        g_wq[i] = packbf(v.x, v.y);
    }
    if (i < NO) {
        float2 v = *(const float2*)(outw + 2 * i);
        g_wo[i] = packbf(v.x, v.y);
    }
}

// ---------------- LayerNorm (fp32 math, bf16 output) ------------------------
__global__ __launch_bounds__(256) void ln_kernel(const float* __restrict__ x,
                                                 const float* __restrict__ w,
                                                 const float* __restrict__ b) {
    int row = blockIdx.x;
    const float4 v = ((const float4*)(x + (size_t)row * DIM))[threadIdx.x];
    float s  = v.x + v.y + v.z + v.w;
    float ss = v.x*v.x + v.y*v.y + v.z*v.z + v.w*v.w;

    __shared__ float sh_s[8], sh_ss[8];
    #pragma unroll
    for (int o = 16; o > 0; o >>= 1) {
        s  += __shfl_xor_sync(0xffffffffu, s,  o);
        ss += __shfl_xor_sync(0xffffffffu, ss, o);
    }
    int wid = threadIdx.x >> 5, lid = threadIdx.x & 31;
    if (lid == 0) { sh_s[wid] = s; sh_ss[wid] = ss; }
    __syncthreads();
    if (wid == 0) {
        s  = (lid < 8) ? sh_s[lid]  : 0.0f;
        ss = (lid < 8) ? sh_ss[lid] : 0.0f;
        #pragma unroll
        for (int o = 4; o > 0; o >>= 1) {
            s  += __shfl_xor_sync(0xffffffffu, s,  o);
            ss += __shfl_xor_sync(0xffffffffu, ss, o);
        }
        if (lid == 0) { sh_s[0] = s; sh_ss[0] = ss; }
    }
    __syncthreads();
    float mean = sh_s[0] * (1.0f / DIM);
    float var  = sh_ss[0] * (1.0f / DIM) - mean * mean;
    float rstd = rsqrtf(var + 1e-5f);

    const float4 wv = ((const float4*)w)[threadIdx.x];
    const float4 bv = ((const float4*)b)[threadIdx.x];
    uint2 out;
    out.x = packbf((v.x - mean) * rstd * wv.x + bv.x,
                   (v.y - mean) * rstd * wv.y + bv.y);
    out.y = packbf((v.z - mean) * rstd * wv.z + bv.z,
                   (v.w - mean) * rstd * wv.w + bv.w);
    *(uint2*)&g_hw[(size_t)row * DIMW + threadIdx.x * 2] = out;
}

// ---------------- bf16 mma.sync GEMM, double-buffered, 2 CTAs/SM -------------
// MODE 0: A=g_hw, B=g_wq, fused bias + per-head L2 norm, f16 scatter to q/k/v.
// MODE 1: A=g_ow, B=g_wo, y = C + bias + x (fp32).
__device__ __forceinline__ void scatter2(int m, int n, float v0, float v1) {
    int which = n >> 10;
    int hn = n & 1023;
    int head = hn >> 6, d = hn & 63;
    unsigned* dst = (which == 0) ? g_qw : (which == 1) ? g_kw : g_vw;
    int bb = m >> 11, t = m & 2047;
    dst[(((size_t)(bb * NH + head)) * SEQ + t) * HDW + (d >> 1)] = packf16(v0, v1);
}

template<int MODE>
__global__ __launch_bounds__(256, 2) void gemm_bf(const float* __restrict__ bias,
                                                  const float* __restrict__ x,
                                                  float* __restrict__ y) {
    const unsigned* Asrc = (MODE == 0) ? g_hw : g_ow;
    const unsigned* Bsrc = (MODE == 0) ? g_wq : g_wo;
    __shared__ unsigned Aw[2][128 * 20];
    __shared__ unsigned Bw[2][128 * 20];

    const int tid = threadIdx.x;
    const int w = tid >> 5, lane = tid & 31;
    const int g = lane >> 2, j = lane & 3;
    const int wm = w & 3, wn = w >> 2;
    const int m0 = blockIdx.y * 128;
    const int n0 = blockIdx.x * 128;

    const unsigned* ag = Asrc + (size_t)m0 * DIMW;
    const unsigned* bg = Bsrc + (size_t)n0 * DIMW;
    const int r0l = tid >> 2, q0l = (tid & 3) * 4;
    const int r1l = (tid + 256) >> 2, q1l = q0l;

    float4 c[2][8];
    #pragma unroll
    for (int mt = 0; mt < 2; mt++)
        #pragma unroll
        for (int nt = 0; nt < 8; nt++) c[mt][nt] = make_float4(0.f, 0.f, 0.f, 0.f);

    uint4 pa0, pa1, pb0, pb1;
    pa0 = *(const uint4*)(ag + (size_t)r0l * DIMW + q0l);
    pa1 = *(const uint4*)(ag + (size_t)r1l * DIMW + q1l);
    pb0 = *(const uint4*)(bg + (size_t)r0l * DIMW + q0l);
    pb1 = *(const uint4*)(bg + (size_t)r1l * DIMW + q1l);
    *(uint4*)&Aw[0][r0l * 20 + q0l] = pa0;
    *(uint4*)&Aw[0][r1l * 20 + q1l] = pa1;
    *(uint4*)&Bw[0][r0l * 20 + q0l] = pb0;
    *(uint4*)&Bw[0][r1l * 20 + q1l] = pb1;
    __syncthreads();

    for (int kt = 0; kt < 32; kt++) {
        const int cur = kt & 1, nxt = cur ^ 1;
        if (kt + 1 < 32) {
            int ko = (kt + 1) * 16;
            pa0 = *(const uint4*)(ag + (size_t)r0l * DIMW + ko + q0l);
            pa1 = *(const uint4*)(ag + (size_t)r1l * DIMW + ko + q1l);
            pb0 = *(const uint4*)(bg + (size_t)r0l * DIMW + ko + q0l);
            pb1 = *(const uint4*)(bg + (size_t)r1l * DIMW + ko + q1l);
        }

        #pragma unroll
        for (int kc = 0; kc < 2; kc++) {
            unsigned a[2][4];
            #pragma unroll
            for (int mt = 0; mt < 2; mt++) {
                int row = wm * 32 + mt * 16 + g;
                a[mt][0] = Aw[cur][row * 20 + kc * 8 + j];
                a[mt][1] = Aw[cur][(row + 8) * 20 + kc * 8 + j];
                a[mt][2] = Aw[cur][row * 20 + kc * 8 + j + 4];
                a[mt][3] = Aw[cur][(row + 8) * 20 + kc * 8 + j + 4];
            }
            unsigned b0[8], b1[8];
            #pragma unroll
            for (int nt = 0; nt < 8; nt++) {
                int n = wn * 64 + nt * 8 + g;
                b0[nt] = Bw[cur][n * 20 + kc * 8 + j];
                b1[nt] = Bw[cur][n * 20 + kc * 8 + j + 4];
            }
            #pragma unroll
            for (int mt = 0; mt < 2; mt++)
                #pragma unroll
                for (int nt = 0; nt < 8; nt++)
                    mmabf(c[mt][nt], a[mt][0], a[mt][1], a[mt][2], a[mt][3],
                          b0[nt], b1[nt]);
        }

        if (kt + 1 < 32) {
            *(uint4*)&Aw[nxt][r0l * 20 + q0l] = pa0;
            *(uint4*)&Aw[nxt][r1l * 20 + q1l] = pa1;
            *(uint4*)&Bw[nxt][r0l * 20 + q0l] = pb0;
            *(uint4*)&Bw[nxt][r1l * 20 + q1l] = pb1;
        }
        __syncthreads();
    }

    if (MODE == 0) {
        // warp's 64-col span = exactly one head; lanes 4g+j form the quad
        const int which = (n0 + wn * 64) >> 10;        // 0=q, 1=k, 2=v
        const float sc = (which == 0) ? QSCALE : 1.0f;
        #pragma unroll
        for (int mt = 0; mt < 2; mt++) {
            int r0 = m0 + wm * 32 + mt * 16 + g;
            int r1 = r0 + 8;
            float v0[16], v1[16];
            float ss0 = 0.f, ss1 = 0.f;
            #pragma unroll
            for (int nt = 0; nt < 8; nt++) {
                int n = n0 + wn * 64 + nt * 8 + 2 * j;
                float bv0 = bias[n], bv1 = bias[n + 1];
                v0[2*nt]   = c[mt][nt].x + bv0;
                v0[2*nt+1] = c[mt][nt].y + bv1;
                v1[2*nt]   = c[mt][nt].z + bv0;
                v1[2*nt+1] = c[mt][nt].w + bv1;
                ss0 += v0[2*nt]*v0[2*nt] + v0[2*nt+1]*v0[2*nt+1];
                ss1 += v1[2*nt]*v1[2*nt] + v1[2*nt+1]*v1[2*nt+1];
            }
            float rn0 = 1.f, rn1 = 1.f;
            if (which < 2) {
                #pragma unroll
                for (int off = 1; off <= 2; off <<= 1) {
                    ss0 += __shfl_xor_sync(0xffffffffu, ss0, off);
                    ss1 += __shfl_xor_sync(0xffffffffu, ss1, off);
                }
                rn0 = sc / fmaxf(sqrtf(ss0), 1e-12f);
                rn1 = sc / fmaxf(sqrtf(ss1), 1e-12f);
            }
            #pragma unroll
            for (int nt = 0; nt < 8; nt++) {
                int n = n0 + wn * 64 + nt * 8 + 2 * j;
                scatter2(r0, n, v0[2*nt] * rn0, v0[2*nt+1] * rn0);
                scatter2(r1, n, v1[2*nt] * rn1, v1[2*nt+1] * rn1);
            }
        }
    } else {
        #pragma unroll
        for (int mt = 0; mt < 2; mt++) {
            int r0 = m0 + wm * 32 + mt * 16 + g;
            int r1 = r0 + 8;
            #pragma unroll
            for (int nt = 0; nt < 8; nt++) {
                int n = n0 + wn * 64 + nt * 8 + 2 * j;
                float bv0 = bias[n], bv1 = bias[n + 1];
                y[(size_t)r0 * DIM + n]     = c[mt][nt].x + bv0 + x[(size_t)r0 * DIM + n];
                y[(size_t)r0 * DIM + n + 1] = c[mt][nt].y + bv1 + x[(size_t)r0 * DIM + n + 1];
                y[(size_t)r1 * DIM + n]     = c[mt][nt].z + bv0 + x[(size_t)r1 * DIM + n];
                y[(size_t)r1 * DIM + n + 1] = c[mt][nt].w + bv1 + x[(size_t)r1 * DIM + n + 1];
            }
        }
    }
}

// ---------------- flash attention: m=32/warp, f16, chunked, 2 CTAs/SM --------
// (unchanged from round 15 — equal-best 225.7us, rel_err 1.0e-4)
__global__ __launch_bounds__(256, 2) void flash_bf() {
    __shared__ unsigned Ksw[2][64 * 36];   // [buf][key][dim-pair word]
    __shared__ unsigned Vsp[2][32 * 72];   // [buf][key-pair][dim word]

    const int tid = threadIdx.x, w = tid >> 5, lane = tid & 31;
    const int g = lane >> 2, j = lane & 3;
    const int bh = blockIdx.y;
    const int q0 = blockIdx.x * 256;

    const unsigned* qw = g_qw + ((size_t)bh * SEQ + q0) * HDW;
    const unsigned* kw = g_kw + (size_t)bh * SEQ * HDW;
    const unsigned* vw = g_vw + (size_t)bh * SEQ * HDW;

    // persistent Q fragments for both m-tiles (f16x2 words)
    unsigned qa[2][4][4];
    #pragma unroll
    for (int mt = 0; mt < 2; mt++) {
        const unsigned* qr  = qw + (size_t)(w * 32 + mt * 16 + g) * HDW;
        const unsigned* qr8 = qr + 8 * HDW;
        #pragma unroll
        for (int kc = 0; kc < 4; kc++) {
            qa[mt][kc][0] = qr [kc * 8 + j];
            qa[mt][kc][1] = qr8[kc * 8 + j];
            qa[mt][kc][2] = qr [kc * 8 + j + 4];
            qa[mt][kc][3] = qr8[kc * 8 + j + 4];
        }
    }

    const int kn  = tid >> 3, kq = (tid & 7) * 4;
    const int kn2 = (tid + 256) >> 3, kq2 = kq;
    const int vp  = tid >> 4, vc = (tid & 15) * 2;
    const int vp2 = (tid + 256) >> 4, vc2 = vc;

#define STAGE(buf, kt) do {                                                     \
    *(uint4*)&Ksw[buf][kn  * 36 + kq ] =                                        \
        *(const uint4*)&kw[(size_t)((kt) + kn ) * HDW + kq ];                   \
    *(uint4*)&Ksw[buf][kn2 * 36 + kq2] =                                        \
        *(const uint4*)&kw[(size_t)((kt) + kn2) * HDW + kq2];                   \
    {                                                                           \
        uint2 w0 = *(const uint2*)&vw[(size_t)((kt) + 2*vp    ) * HDW + vc ];   \
        uint2 w1 = *(const uint2*)&vw[(size_t)((kt) + 2*vp + 1) * HDW + vc ];   \
        uint4 ov;                                                               \
        ov.x = prmt(w0.x, w1.x, 0x5410u); ov.y = prmt(w0.x, w1.x, 0x7632u);     \
        ov.z = prmt(w0.y, w1.y, 0x5410u); ov.w = prmt(w0.y, w1.y, 0x7632u);     \
        *(uint4*)&Vsp[buf][vp * 72 + vc * 2] = ov;                              \
        w0 = *(const uint2*)&vw[(size_t)((kt) + 2*vp2    ) * HDW + vc2];        \
        w1 = *(const uint2*)&vw[(size_t)((kt) + 2*vp2 + 1) * HDW + vc2];        \
        ov.x = prmt(w0.x, w1.x, 0x5410u); ov.y = prmt(w0.x, w1.x, 0x7632u);     \
        ov.z = prmt(w0.y, w1.y, 0x5410u); ov.w = prmt(w0.y, w1.y, 0x7632u);     \
        *(uint4*)&Vsp[buf][vp2 * 72 + vc2 * 2] = ov;                            \
    }                                                                           \
} while (0)

    // O accumulators in f16x2: [mt][nt] -> 2 packed regs each
    unsigned o0[2][8], o1[2][8];
    #pragma unroll
    for (int mt = 0; mt < 2; mt++)
        #pragma unroll
        for (int nt = 0; nt < 8; nt++) { o0[mt][nt] = 0u; o1[mt][nt] = 0u; }
    float l0[2] = {0.f, 0.f}, l1[2] = {0.f, 0.f};

    STAGE(0, 0);
    __syncthreads();

    for (int it = 0; it < SEQ / 64; it++) {
        const int cur = it & 1;
        if (it + 1 < SEQ / 64) STAGE(cur ^ 1, (it + 1) * 64);

        // 4 chunks of 16 keys; K/V fragments loaded once, used by both m-tiles
        #pragma unroll
        for (int p = 0; p < 4; p++) {
            float4 c00 = make_float4(0.f, 0.f, 0.f, 0.f);
            float4 c01 = make_float4(0.f, 0.f, 0.f, 0.f);
            float4 c10 = make_float4(0.f, 0.f, 0.f, 0.f);
            float4 c11 = make_float4(0.f, 0.f, 0.f, 0.f);
            const int kb0 = ((2 * p)     * 8 + g) * 36;
            const int kb1 = ((2 * p + 1) * 8 + g) * 36;
            #pragma unroll
            for (int kc = 0; kc < 4; kc++) {
                unsigned b00 = Ksw[cur][kb0 + kc * 8 + j];
                unsigned b01 = Ksw[cur][kb0 + kc * 8 + j + 4];
                unsigned b10 = Ksw[cur][kb1 + kc * 8 + j];
                unsigned b11 = Ksw[cur][kb1 + kc * 8 + j + 4];
                mmaf16s(c00, qa[0][kc][0], qa[0][kc][1], qa[0][kc][2], qa[0][kc][3], b00, b01);
                mmaf16s(c10, qa[1][kc][0], qa[1][kc][1], qa[1][kc][2], qa[1][kc][3], b00, b01);
                mmaf16s(c01, qa[0][kc][0], qa[0][kc][1], qa[0][kc][2], qa[0][kc][3], b10, b11);
                mmaf16s(c11, qa[1][kc][0], qa[1][kc][1], qa[1][kc][2], qa[1][kc][3], b10, b11);
            }
            // fixed-max softmax (exp2 domain)
            c00.x = ex2(c00.x - FIXED_MAX); c00.y = ex2(c00.y - FIXED_MAX);
            c00.z = ex2(c00.z - FIXED_MAX); c00.w = ex2(c00.w - FIXED_MAX);
            c01.x = ex2(c01.x - FIXED_MAX); c01.y = ex2(c01.y - FIXED_MAX);
            c01.z = ex2(c01.z - FIXED_MAX); c01.w = ex2(c01.w - FIXED_MAX);
            c10.x = ex2(c10.x - FIXED_MAX); c10.y = ex2(c10.y - FIXED_MAX);
            c10.z = ex2(c10.z - FIXED_MAX); c10.w = ex2(c10.w - FIXED_MAX);
            c11.x = ex2(c11.x - FIXED_MAX); c11.y = ex2(c11.y - FIXED_MAX);
            c11.z = ex2(c11.z - FIXED_MAX); c11.w = ex2(c11.w - FIXED_MAX);
            l0[0] += c00.x + c00.y + c01.x + c01.y;
            l1[0] += c00.z + c00.w + c01.z + c01.w;
            l0[1] += c10.x + c10.y + c11.x + c11.y;
            l1[1] += c10.z + c10.w + c11.z + c11.w;
            unsigned a00 = packf16(c00.x, c00.y);
            unsigned a01 = packf16(c00.z, c00.w);
            unsigned a02 = packf16(c01.x, c01.y);
            unsigned a03 = packf16(c01.z, c01.w);
            unsigned a10 = packf16(c10.x, c10.y);
            unsigned a11 = packf16(c10.z, c10.w);
            unsigned a12 = packf16(c11.x, c11.y);
            unsigned a13 = packf16(c11.z, c11.w);
            const int vb0 = (p * 8 + j) * 72;
            const int vb1 = (p * 8 + j + 4) * 72;
            #pragma unroll
            for (int nt = 0; nt < 8; nt++) {
                unsigned b0 = Vsp[cur][vb0 + nt * 8 + g];
                unsigned b1 = Vsp[cur][vb1 + nt * 8 + g];
                mmaf16a(o0[0][nt], o1[0][nt], a00, a01, a02, a03, b0, b1);
                mmaf16a(o0[1][nt], o1[1][nt], a10, a11, a12, a13, b0, b1);
            }
        }
        __syncthreads();
    }

    const int b = bh >> 4, head = bh & 15;
    #pragma unroll
    for (int mt = 0; mt < 2; mt++) {
        float s0 = l0[mt], s1 = l1[mt];
        #pragma unroll
        for (int off = 1; off <= 2; off <<= 1) {
            s0 += __shfl_xor_sync(0xffffffffu, s0, off);
            s1 += __shfl_xor_sync(0xffffffffu, s1, off);
        }
        float inv0 = 1.0f / s0, inv1 = 1.0f / s1;
        size_t row0 = ((size_t)(b * SEQ + q0 + w * 32 + mt * 16 + g)) * DIMW + head * 32;
        size_t row1 = row0 + (size_t)8 * DIMW;
        #pragma unroll
        for (int nt = 0; nt < 8; nt++) {
            float2 f0 = __half22float2(*reinterpret_cast<__half2*>(&o0[mt][nt]));
            float2 f1 = __half22float2(*reinterpret_cast<__half2*>(&o1[mt][nt]));
            g_ow[row0 + nt * 4 + j] = packbf(f0.x * inv0, f0.y * inv0);
            g_ow[row1 + nt * 4 + j] = packbf(f1.x * inv1, f1.y * inv1);
        }
    }
#undef STAGE
}

// ---------------- launch -----------------------------------------------------
extern "C" void kernel_launch(void* const* d_in, const int* in_sizes, int n_in,
                              void* d_out, int out_size) {
    const float* x     = (const float*)d_in[0];
    const float* ln_w  = (const float*)d_in[1];
    const float* ln_b  = (const float*)d_in[2];
    const float* qkv_w = (const float*)d_in[3];
    const float* qkv_b = (const float*)d_in[4];
    const float* out_w = (const float*)d_in[5];
    const float* out_b = (const float*)d_in[6];
    float* y = (float*)d_out;

    wconv<<<(N3 * DIMW) / 256, 256>>>(qkv_w, out_w);

    ln_kernel<<<MROWS, 256>>>(x, ln_w, ln_b);

    gemm_bf<0><<<dim3(N3 / 128, MROWS / 128), 256>>>(qkv_b, nullptr, nullptr);

    flash_bf<<<dim3(SEQ / 256, BATCH * NH), 256>>>();

    gemm_bf<1><<<dim3(DIM / 128, MROWS / 128), 256>>>(out_b, x, y);
}

// round 17
// speedup vs baseline: 1.1535x; 1.0303x over previous
#include <cuda_runtime.h>
#include <cuda_fp16.h>
#include <math.h>
#include <stdint.h>

#define BATCH 4
#define SEQ   2048
#define DIM   1024
#define DIMW  512            // 16-bit-pair words per row
#define NH    16
#define HD    64
#define HDW   32             // 16-bit-pair words per head row
#define MROWS (BATCH*SEQ)    // 8192
#define N3    (3*DIM)        // 3072
#define NROWS (BATCH*NH*SEQ) // 131072 head rows

// logit bound in exp2 domain: 8*log2(e) = 11.5416
#define FIXED_MAX 11.6f
#define QSCALE (8.0f * 1.4426950408889634f)

// ---------------- scratch (device globals; referenced ONLY in device code) --
__device__ __align__(16) unsigned g_hw[MROWS * DIMW];        // LN out, bf16x2
__device__ __align__(16) unsigned g_wq[(size_t)N3 * DIMW];   // qkv_w bf16
__device__ __align__(16) unsigned g_wo[(size_t)DIM * DIMW];  // out_w bf16
__device__ __align__(16) unsigned g_qw[(size_t)NROWS * HDW]; // q f16 [bh][t][dw]
__device__ __align__(16) unsigned g_kw[(size_t)NROWS * HDW]; // k f16
__device__ __align__(16) unsigned g_vw[(size_t)NROWS * HDW]; // v f16
__device__ __align__(16) unsigned g_ow[MROWS * DIMW];        // attn out, bf16x2

// ---------------- helpers -----------------------------------------------------
__device__ __forceinline__ unsigned packbf(float lo, float hi) {
    unsigned d;
    asm("cvt.rn.bf16x2.f32 %0, %1, %2;" : "=r"(d) : "f"(hi), "f"(lo));
    return d;
}
__device__ __forceinline__ unsigned packf16(float lo, float hi) {
    __half2 h = __floats2half2_rn(lo, hi);
    return *reinterpret_cast<unsigned*>(&h);
}
__device__ __forceinline__ unsigned ex2h2(unsigned x) {
    unsigned r;
    asm("ex2.approx.f16x2 %0, %1;" : "=r"(r) : "r"(x));
    return r;
}
__device__ __forceinline__ unsigned prmt(unsigned a, unsigned b, unsigned s) {
    unsigned d;
    asm("prmt.b32 %0, %1, %2, %3;" : "=r"(d) : "r"(a), "r"(b), "r"(s));
    return d;
}
__device__ __forceinline__ uint32_t smem_u32(const void* p) {
    uint32_t a;
    asm("{ .reg .u64 t; cvta.to.shared.u64 t, %1; cvt.u32.u64 %0, t; }"
        : "=r"(a) : "l"(p));
    return a;
}
__device__ __forceinline__ void cpasync16(uint32_t saddr, const void* g) {
    asm volatile("cp.async.cg.shared.global [%0], [%1], 16;"
                 :: "r"(saddr), "l"(g) : "memory");
}
#define CP_COMMIT() asm volatile("cp.async.commit_group;" ::: "memory")
#define CP_WAIT2()  asm volatile("cp.async.wait_group 2;" ::: "memory")

// bf16 in, f32 acc (GEMM)
__device__ __forceinline__ void mmabf(float4& d, unsigned a0, unsigned a1,
                                      unsigned a2, unsigned a3,
                                      unsigned b0, unsigned b1) {
    asm volatile(
        "mma.sync.aligned.m16n8k16.row.col.f32.bf16.bf16.f32 "
        "{%0,%1,%2,%3}, {%4,%5,%6,%7}, {%8,%9}, {%0,%1,%2,%3};\n"
        : "+f"(d.x), "+f"(d.y), "+f"(d.z), "+f"(d.w)
        : "r"(a0), "r"(a1), "r"(a2), "r"(a3), "r"(b0), "r"(b1));
}
// f16 in, f32 acc (flash S)
__device__ __forceinline__ void mmaf16s(float4& d, unsigned a0, unsigned a1,
                                        unsigned a2, unsigned a3,
                                        unsigned b0, unsigned b1) {
    asm volatile(
        "mma.sync.aligned.m16n8k16.row.col.f32.f16.f16.f32 "
        "{%0,%1,%2,%3}, {%4,%5,%6,%7}, {%8,%9}, {%0,%1,%2,%3};\n"
        : "+f"(d.x), "+f"(d.y), "+f"(d.z), "+f"(d.w)
        : "r"(a0), "r"(a1), "r"(a2), "r"(a3), "r"(b0), "r"(b1));
}
// f16 in, f16 acc (flash PV)
__device__ __forceinline__ void mmaf16a(unsigned& d0, unsigned& d1,
                                        unsigned a0, unsigned a1,
                                        unsigned a2, unsigned a3,
                                        unsigned b0, unsigned b1) {
    asm volatile(
        "mma.sync.aligned.m16n8k16.row.col.f16.f16.f16.f16 "
        "{%0,%1}, {%2,%3,%4,%5}, {%6,%7}, {%0,%1};\n"
        : "+r"(d0), "+r"(d1)
        : "r"(a0), "r"(a1), "r"(a2), "r"(a3), "r"(b0), "r"(b1));
}

// ---------------- weight fp32 -> bf16 conversion (once per call) -------------
__global__ __launch_bounds__(256) void wconv(const float* __restrict__ qkvw,
                                             const float* __restrict__ outw) {
    size_t i = (size_t)blockIdx.x * 256 + threadIdx.x;
    const size_t NQ = (size_t)N3 * DIMW;
    const size_t NO = (size_t)DIM * DIMW;
    if (i < NQ) {
        float2 v = *(const float2*)(qkvw + 2 * i);
        g_wq[i] = packbf(v.x, v.y);
    }
    if (i < NO) {
        float2 v = *(const float2*)(outw + 2 * i);
        g_wo[i] = packbf(v.x, v.y);
    }
}

// ---------------- LayerNorm (fp32 math, bf16 output) ------------------------
__global__ __launch_bounds__(256) void ln_kernel(const float* __restrict__ x,
                                                 const float* __restrict__ w,
                                                 const float* __restrict__ b) {
    int row = blockIdx.x;
    const float4 v = ((const float4*)(x + (size_t)row * DIM))[threadIdx.x];
    float s  = v.x + v.y + v.z + v.w;
    float ss = v.x*v.x + v.y*v.y + v.z*v.z + v.w*v.w;

    __shared__ float sh_s[8], sh_ss[8];
    #pragma unroll
    for (int o = 16; o > 0; o >>= 1) {
        s  += __shfl_xor_sync(0xffffffffu, s,  o);
        ss += __shfl_xor_sync(0xffffffffu, ss, o);
    }
    int wid = threadIdx.x >> 5, lid = threadIdx.x & 31;
    if (lid == 0) { sh_s[wid] = s; sh_ss[wid] = ss; }
    __syncthreads();
    if (wid == 0) {
        s  = (lid < 8) ? sh_s[lid]  : 0.0f;
        ss = (lid < 8) ? sh_ss[lid] : 0.0f;
        #pragma unroll
        for (int o = 4; o > 0; o >>= 1) {
            s  += __shfl_xor_sync(0xffffffffu, s,  o);
            ss += __shfl_xor_sync(0xffffffffu, ss, o);
        }
        if (lid == 0) { sh_s[0] = s; sh_ss[0] = ss; }
    }
    __syncthreads();
    float mean = sh_s[0] * (1.0f / DIM);
    float var  = sh_ss[0] * (1.0f / DIM) - mean * mean;
    float rstd = rsqrtf(var + 1e-5f);

    const float4 wv = ((const float4*)w)[threadIdx.x];
    const float4 bv = ((const float4*)b)[threadIdx.x];
    uint2 out;
    out.x = packbf((v.x - mean) * rstd * wv.x + bv.x,
                   (v.y - mean) * rstd * wv.y + bv.y);
    out.y = packbf((v.z - mean) * rstd * wv.z + bv.z,
                   (v.w - mean) * rstd * wv.w + bv.w);
    *(uint2*)&g_hw[(size_t)row * DIMW + threadIdx.x * 2] = out;
}

// ---------------- bf16 mma.sync GEMM, cp.async 4-stage, 2 CTAs/SM ------------
// MODE 0: A=g_hw, B=g_wq, fused bias + per-head L2 norm, f16 scatter to q/k/v.
// MODE 1: A=g_ow, B=g_wo, y = C + bias + x (fp32).
#define STG_WORDS   (128 * 20)          // one tensor, one stage (padded)
#define STAGE_WORDS (2 * STG_WORDS)     // A + B
#define GEMM_SMEM   (4 * STAGE_WORDS * 4)  // 81920 bytes

__device__ __forceinline__ void scatter2(int m, int n, float v0, float v1) {
    int which = n >> 10;
    int hn = n & 1023;
    int head = hn >> 6, d = hn & 63;
    unsigned* dst = (which == 0) ? g_qw : (which == 1) ? g_kw : g_vw;
    int bb = m >> 11, t = m & 2047;
    dst[(((size_t)(bb * NH + head)) * SEQ + t) * HDW + (d >> 1)] = packf16(v0, v1);
}

template<int MODE>
__global__ __launch_bounds__(256, 2) void gemm_bf(const float* __restrict__ bias,
                                                  const float* __restrict__ x,
                                                  float* __restrict__ y) {
    extern __shared__ unsigned dyn[];
    const unsigned* Asrc = (MODE == 0) ? g_hw : g_ow;
    const unsigned* Bsrc = (MODE == 0) ? g_wq : g_wo;

    const int tid = threadIdx.x;
    const int w = tid >> 5, lane = tid & 31;
    const int g = lane >> 2, j = lane & 3;
    const int wm = w & 3, wn = w >> 2;
    const int m0 = blockIdx.y * 128;
    const int n0 = blockIdx.x * 128;

    const unsigned* ag = Asrc + (size_t)m0 * DIMW;
    const unsigned* bg = Bsrc + (size_t)n0 * DIMW;
    const int r0l = tid >> 2, q0l = (tid & 3) * 4;
    const int r1l = (tid + 256) >> 2;

    const uint32_t sbase = smem_u32(dyn);

    float4 c[2][8];
    #pragma unroll
    for (int mt = 0; mt < 2; mt++)
        #pragma unroll
        for (int nt = 0; nt < 8; nt++) c[mt][nt] = make_float4(0.f, 0.f, 0.f, 0.f);

#define ISSUE(s, kt) do {                                                       \
    uint32_t as_ = sbase + (uint32_t)((s) * STAGE_WORDS) * 4u;                  \
    uint32_t bs_ = as_ + (uint32_t)STG_WORDS * 4u;                              \
    int ko_ = (kt) * 16;                                                        \
    cpasync16(as_ + (r0l * 20 + q0l) * 4, ag + (size_t)r0l * DIMW + ko_ + q0l); \
    cpasync16(as_ + (r1l * 20 + q0l) * 4, ag + (size_t)r1l * DIMW + ko_ + q0l); \
    cpasync16(bs_ + (r0l * 20 + q0l) * 4, bg + (size_t)r0l * DIMW + ko_ + q0l); \
    cpasync16(bs_ + (r1l * 20 + q0l) * 4, bg + (size_t)r1l * DIMW + ko_ + q0l); \
} while (0)

    ISSUE(0, 0); CP_COMMIT();
    ISSUE(1, 1); CP_COMMIT();
    ISSUE(2, 2); CP_COMMIT();

    for (int kt = 0; kt < 32; kt++) {
        CP_WAIT2();
        __syncthreads();
        if (kt + 3 < 32) ISSUE((kt + 3) & 3, kt + 3);
        CP_COMMIT();

        const unsigned* Aw = dyn + (kt & 3) * STAGE_WORDS;
        const unsigned* Bw = Aw + STG_WORDS;
        #pragma unroll
        for (int kc = 0; kc < 2; kc++) {
            unsigned a[2][4];
            #pragma unroll
            for (int mt = 0; mt < 2; mt++) {
                int row = wm * 32 + mt * 16 + g;
                a[mt][0] = Aw[row * 20 + kc * 8 + j];
                a[mt][1] = Aw[(row + 8) * 20 + kc * 8 + j];
                a[mt][2] = Aw[row * 20 + kc * 8 + j + 4];
                a[mt][3] = Aw[(row + 8) * 20 + kc * 8 + j + 4];
            }
            unsigned b0[8], b1[8];
            #pragma unroll
            for (int nt = 0; nt < 8; nt++) {
                int n = wn * 64 + nt * 8 + g;
                b0[nt] = Bw[n * 20 + kc * 8 + j];
                b1[nt] = Bw[n * 20 + kc * 8 + j + 4];
            }
            #pragma unroll
            for (int mt = 0; mt < 2; mt++)
                #pragma unroll
                for (int nt = 0; nt < 8; nt++)
                    mmabf(c[mt][nt], a[mt][0], a[mt][1], a[mt][2], a[mt][3],
                          b0[nt], b1[nt]);
        }
    }
#undef ISSUE

    if (MODE == 0) {
        const int which = (n0 + wn * 64) >> 10;        // 0=q, 1=k, 2=v
        const float sc = (which == 0) ? QSCALE : 1.0f;
        #pragma unroll
        for (int mt = 0; mt < 2; mt++) {
            int r0 = m0 + wm * 32 + mt * 16 + g;
            int r1 = r0 + 8;
            float v0[16], v1[16];
            float ss0 = 0.f, ss1 = 0.f;
            #pragma unroll
            for (int nt = 0; nt < 8; nt++) {
                int n = n0 + wn * 64 + nt * 8 + 2 * j;
                float bv0 = bias[n], bv1 = bias[n + 1];
                v0[2*nt]   = c[mt][nt].x + bv0;
                v0[2*nt+1] = c[mt][nt].y + bv1;
                v1[2*nt]   = c[mt][nt].z + bv0;
                v1[2*nt+1] = c[mt][nt].w + bv1;
                ss0 += v0[2*nt]*v0[2*nt] + v0[2*nt+1]*v0[2*nt+1];
                ss1 += v1[2*nt]*v1[2*nt] + v1[2*nt+1]*v1[2*nt+1];
            }
            float rn0 = 1.f, rn1 = 1.f;
            if (which < 2) {
                #pragma unroll
                for (int off = 1; off <= 2; off <<= 1) {
                    ss0 += __shfl_xor_sync(0xffffffffu, ss0, off);
                    ss1 += __shfl_xor_sync(0xffffffffu, ss1, off);
                }
                rn0 = sc / fmaxf(sqrtf(ss0), 1e-12f);
                rn1 = sc / fmaxf(sqrtf(ss1), 1e-12f);
            }
            #pragma unroll
            for (int nt = 0; nt < 8; nt++) {
                int n = n0 + wn * 64 + nt * 8 + 2 * j;
                scatter2(r0, n, v0[2*nt] * rn0, v0[2*nt+1] * rn0);
                scatter2(r1, n, v1[2*nt] * rn1, v1[2*nt+1] * rn1);
            }
        }
    } else {
        #pragma unroll
        for (int mt = 0; mt < 2; mt++) {
            int r0 = m0 + wm * 32 + mt * 16 + g;
            int r1 = r0 + 8;
            #pragma unroll
            for (int nt = 0; nt < 8; nt++) {
                int n = n0 + wn * 64 + nt * 8 + 2 * j;
                float bv0 = bias[n], bv1 = bias[n + 1];
                y[(size_t)r0 * DIM + n]     = c[mt][nt].x + bv0 + x[(size_t)r0 * DIM + n];
                y[(size_t)r0 * DIM + n + 1] = c[mt][nt].y + bv1 + x[(size_t)r0 * DIM + n + 1];
                y[(size_t)r1 * DIM + n]     = c[mt][nt].z + bv0 + x[(size_t)r1 * DIM + n];
                y[(size_t)r1 * DIM + n + 1] = c[mt][nt].w + bv1 + x[(size_t)r1 * DIM + n + 1];
            }
        }
    }
}

// ---------------- flash attention: m=32/warp, f16, ex2.f16x2, 2 CTAs/SM ------
__global__ __launch_bounds__(256, 2) void flash_bf() {
    __shared__ unsigned Ksw[2][64 * 36];   // [buf][key][dim-pair word]
    __shared__ unsigned Vsp[2][32 * 72];   // [buf][key-pair][dim word]

    const int tid = threadIdx.x, w = tid >> 5, lane = tid & 31;
    const int g = lane >> 2, j = lane & 3;
    const int bh = blockIdx.y;
    const int q0 = blockIdx.x * 256;

    const unsigned* qw = g_qw + ((size_t)bh * SEQ + q0) * HDW;
    const unsigned* kw = g_kw + (size_t)bh * SEQ * HDW;
    const unsigned* vw = g_vw + (size_t)bh * SEQ * HDW;

    // persistent Q fragments for both m-tiles (f16x2 words)
    unsigned qa[2][4][4];
    #pragma unroll
    for (int mt = 0; mt < 2; mt++) {
        const unsigned* qr  = qw + (size_t)(w * 32 + mt * 16 + g) * HDW;
        const unsigned* qr8 = qr + 8 * HDW;
        #pragma unroll
        for (int kc = 0; kc < 4; kc++) {
            qa[mt][kc][0] = qr [kc * 8 + j];
            qa[mt][kc][1] = qr8[kc * 8 + j];
            qa[mt][kc][2] = qr [kc * 8 + j + 4];
            qa[mt][kc][3] = qr8[kc * 8 + j + 4];
        }
    }

    const int kn  = tid >> 3, kq = (tid & 7) * 4;
    const int kn2 = (tid + 256) >> 3, kq2 = kq;
    const int vp  = tid >> 4, vc = (tid & 15) * 2;
    const int vp2 = (tid + 256) >> 4, vc2 = vc;

#define STAGE(buf, kt) do {                                                     \
    *(uint4*)&Ksw[buf][kn  * 36 + kq ] =                                        \
        *(const uint4*)&kw[(size_t)((kt) + kn ) * HDW + kq ];                   \
    *(uint4*)&Ksw[buf][kn2 * 36 + kq2] =                                        \
        *(const uint4*)&kw[(size_t)((kt) + kn2) * HDW + kq2];                   \
    {                                                                           \
        uint2 w0 = *(const uint2*)&vw[(size_t)((kt) + 2*vp    ) * HDW + vc ];   \
        uint2 w1 = *(const uint2*)&vw[(size_t)((kt) + 2*vp + 1) * HDW + vc ];   \
        uint4 ov;                                                               \
        ov.x = prmt(w0.x, w1.x, 0x5410u); ov.y = prmt(w0.x, w1.x, 0x7632u);     \
        ov.z = prmt(w0.y, w1.y, 0x5410u); ov.w = prmt(w0.y, w1.y, 0x7632u);     \
        *(uint4*)&Vsp[buf][vp * 72 + vc * 2] = ov;                              \
        w0 = *(const uint2*)&vw[(size_t)((kt) + 2*vp2    ) * HDW + vc2];        \
        w1 = *(const uint2*)&vw[(size_t)((kt) + 2*vp2 + 1) * HDW + vc2];        \
        ov.x = prmt(w0.x, w1.x, 0x5410u); ov.y = prmt(w0.x, w1.x, 0x7632u);     \
        ov.z = prmt(w0.y, w1.y, 0x5410u); ov.w = prmt(w0.y, w1.y, 0x7632u);     \
        *(uint4*)&Vsp[buf][vp2 * 72 + vc2 * 2] = ov;                            \
    }                                                                           \
} while (0)

    unsigned o0[2][8], o1[2][8];
    #pragma unroll
    for (int mt = 0; mt < 2; mt++)
        #pragma unroll
        for (int nt = 0; nt < 8; nt++) { o0[mt][nt] = 0u; o1[mt][nt] = 0u; }
    float l0[2] = {0.f, 0.f}, l1[2] = {0.f, 0.f};

    STAGE(0, 0);
    __syncthreads();

    for (int it = 0; it < SEQ / 64; it++) {
        const int cur = it & 1;
        if (it + 1 < SEQ / 64) STAGE(cur ^ 1, (it + 1) * 64);

        #pragma unroll
        for (int p = 0; p < 4; p++) {
            float4 c00 = make_float4(0.f, 0.f, 0.f, 0.f);
            float4 c01 = make_float4(0.f, 0.f, 0.f, 0.f);
            float4 c10 = make_float4(0.f, 0.f, 0.f, 0.f);
            float4 c11 = make_float4(0.f, 0.f, 0.f, 0.f);
            const int kb0 = ((2 * p)     * 8 + g) * 36;
            const int kb1 = ((2 * p + 1) * 8 + g) * 36;
            #pragma unroll
            for (int kc = 0; kc < 4; kc++) {
                unsigned b00 = Ksw[cur][kb0 + kc * 8 + j];
                unsigned b01 = Ksw[cur][kb0 + kc * 8 + j + 4];
                unsigned b10 = Ksw[cur][kb1 + kc * 8 + j];
                unsigned b11 = Ksw[cur][kb1 + kc * 8 + j + 4];
                mmaf16s(c00, qa[0][kc][0], qa[0][kc][1], qa[0][kc][2], qa[0][kc][3], b00, b01);
                mmaf16s(c10, qa[1][kc][0], qa[1][kc][1], qa[1][kc][2], qa[1][kc][3], b00, b01);
                mmaf16s(c01, qa[0][kc][0], qa[0][kc][1], qa[0][kc][2], qa[0][kc][3], b10, b11);
                mmaf16s(c11, qa[1][kc][0], qa[1][kc][1], qa[1][kc][2], qa[1][kc][3], b10, b11);
            }
            // fixed-max softmax: subtract C in f32, pack, ONE packed ex2 per word
            unsigned a00 = ex2h2(packf16(c00.x - FIXED_MAX, c00.y - FIXED_MAX));
            unsigned a01 = ex2h2(packf16(c00.z - FIXED_MAX, c00.w - FIXED_MAX));
            unsigned a02 = ex2h2(packf16(c01.x - FIXED_MAX, c01.y - FIXED_MAX));
            unsigned a03 = ex2h2(packf16(c01.z - FIXED_MAX, c01.w - FIXED_MAX));
            unsigned a10 = ex2h2(packf16(c10.x - FIXED_MAX, c10.y - FIXED_MAX));
            unsigned a11 = ex2h2(packf16(c10.z - FIXED_MAX, c10.w - FIXED_MAX));
            unsigned a12 = ex2h2(packf16(c11.x - FIXED_MAX, c11.y - FIXED_MAX));
            unsigned a13 = ex2h2(packf16(c11.z - FIXED_MAX, c11.w - FIXED_MAX));
            // l sums: HADD2 pairs (f16, error ~2^-11), accumulate in f32
            {
                __half2 h;
                float2 f;
                h = __hadd2(*reinterpret_cast<__half2*>(&a00),
                            *reinterpret_cast<__half2*>(&a02));
                f = __half22float2(h); l0[0] += f.x + f.y;
                h = __hadd2(*reinterpret_cast<__half2*>(&a01),
                            *reinterpret_cast<__half2*>(&a03));
                f = __half22float2(h); l1[0] += f.x + f.y;
                h = __hadd2(*reinterpret_cast<__half2*>(&a10),
                            *reinterpret_cast<__half2*>(&a12));
                f = __half22float2(h); l0[1] += f.x + f.y;
                h = __hadd2(*reinterpret_cast<__half2*>(&a11),
                            *reinterpret_cast<__half2*>(&a13));
                f = __half22float2(h); l1[1] += f.x + f.y;
            }
            const int vb0 = (p * 8 + j) * 72;
            const int vb1 = (p * 8 + j + 4) * 72;
            #pragma unroll
            for (int nt = 0; nt < 8; nt++) {
                unsigned b0 = Vsp[cur][vb0 + nt * 8 + g];
                unsigned b1 = Vsp[cur][vb1 + nt * 8 + g];
                mmaf16a(o0[0][nt], o1[0][nt], a00, a01, a02, a03, b0, b1);
                mmaf16a(o0[1][nt], o1[1][nt], a10, a11, a12, a13, b0, b1);
            }
        }
        __syncthreads();
    }

    const int b = bh >> 4, head = bh & 15;
    #pragma unroll
    for (int mt = 0; mt < 2; mt++) {
        float s0 = l0[mt], s1 = l1[mt];
        #pragma unroll
        for (int off = 1; off <= 2; off <<= 1) {
            s0 += __shfl_xor_sync(0xffffffffu, s0, off);
            s1 += __shfl_xor_sync(0xffffffffu, s1, off);
        }
        float inv0 = 1.0f / s0, inv1 = 1.0f / s1;
        size_t row0 = ((size_t)(b * SEQ + q0 + w * 32 + mt * 16 + g)) * DIMW + head * 32;
        size_t row1 = row0 + (size_t)8 * DIMW;
        #pragma unroll
        for (int nt = 0; nt < 8; nt++) {
            float2 f0 = __half22float2(*reinterpret_cast<__half2*>(&o0[mt][nt]));
            float2 f1 = __half22float2(*reinterpret_cast<__half2*>(&o1[mt][nt]));
            g_ow[row0 + nt * 4 + j] = packbf(f0.x * inv0, f0.y * inv0);
            g_ow[row1 + nt * 4 + j] = packbf(f1.x * inv1, f1.y * inv1);
        }
    }
#undef STAGE
}

// ---------------- launch -----------------------------------------------------
extern "C" void kernel_launch(void* const* d_in, const int* in_sizes, int n_in,
                              void* d_out, int out_size) {
    const float* x     = (const float*)d_in[0];
    const float* ln_w  = (const float*)d_in[1];
    const float* ln_b  = (const float*)d_in[2];
    const float* qkv_w = (const float*)d_in[3];
    const float* qkv_b = (const float*)d_in[4];
    const float* out_w = (const float*)d_in[5];
    const float* out_b = (const float*)d_in[6];
    float* y = (float*)d_out;

    cudaFuncSetAttribute(gemm_bf<0>, cudaFuncAttributeMaxDynamicSharedMemorySize, GEMM_SMEM);
    cudaFuncSetAttribute(gemm_bf<1>, cudaFuncAttributeMaxDynamicSharedMemorySize, GEMM_SMEM);

    wconv<<<(N3 * DIMW) / 256, 256>>>(qkv_w, out_w);

    ln_kernel<<<MROWS, 256>>>(x, ln_w, ln_b);

    gemm_bf<0><<<dim3(N3 / 128, MROWS / 128), 256, GEMM_SMEM>>>(qkv_b, nullptr, nullptr);

    flash_bf<<<dim3(SEQ / 256, BATCH * NH), 256>>>();

    gemm_bf<1><<<dim3(DIM / 128, MROWS / 128), 256, GEMM_SMEM>>>(out_b, x, y);
}